// round 1
// baseline (speedup 1.0000x reference)
#include <cuda_runtime.h>
#include <math.h>

#define BB 2
#define LL 2048
#define DD 1024
#define HH 16
#define HD 64
#define FF 4096
#define MROWS (BB*LL)   // 4096

// ---------------- scratch (device globals; no allocation allowed) ----------
__device__ float g_xn  [MROWS * DD];       // LN1 output
__device__ float g_qkuv[MROWS * 4 * DD];   // silu(xn @ w_qkuv)
__device__ float g_a   [MROWS * DD];       // attention output (post headLN * u), [B,L,D]
__device__ float g_x1  [MROWS * DD];       // x + a @ w_out
__device__ float g_xn2 [MROWS * DD];       // LN2 output
__device__ float g_h1  [MROWS * FF];       // silu(xn2 @ w1)
__device__ float g_h   [MROWS * FF];       // h1 * (xn2 @ w3)

__device__ __forceinline__ float silu(float x) {
    return x / (1.0f + expf(-x));
}

// ---------------- LayerNorm over last dim D=1024 ---------------------------
__global__ __launch_bounds__(256) void ln_kernel(
    const float* __restrict__ x, const float* __restrict__ g,
    const float* __restrict__ b, float* __restrict__ out)
{
    int row = blockIdx.x;
    const float* xr = x + (size_t)row * DD;
    float* outr = out + (size_t)row * DD;

    float s = 0.f, s2 = 0.f;
    for (int i = threadIdx.x; i < DD; i += 256) {
        float v = xr[i];
        s += v; s2 += v * v;
    }
    __shared__ float red[16];
    __shared__ float red2[16];
    __shared__ float stats[2];
    for (int off = 16; off > 0; off >>= 1) {
        s  += __shfl_down_sync(0xffffffffu, s,  off);
        s2 += __shfl_down_sync(0xffffffffu, s2, off);
    }
    int wid = threadIdx.x >> 5, lid = threadIdx.x & 31;
    if (lid == 0) { red[wid] = s; red2[wid] = s2; }
    __syncthreads();
    if (threadIdx.x == 0) {
        float ts = 0.f, ts2 = 0.f;
        for (int i = 0; i < 8; i++) { ts += red[i]; ts2 += red2[i]; }
        float mu = ts * (1.0f / DD);
        float var = ts2 * (1.0f / DD) - mu * mu;
        stats[0] = mu;
        stats[1] = rsqrtf(var + 1e-5f);
    }
    __syncthreads();
    float mu = stats[0], rstd = stats[1];
    for (int i = threadIdx.x; i < DD; i += 256) {
        outr[i] = (xr[i] - mu) * rstd * g[i] + b[i];
    }
}

// ---------------- SGEMM: C[M,N] = epi(A[M,K] @ W[K,N]) ---------------------
// MODE: 1 = silu(acc), 2 = acc + aux, 3 = acc * aux
// BM=BN=128, BK=16, 256 threads, 8x8 per thread.
template <int MODE>
__global__ __launch_bounds__(256) void sgemm_kernel(
    const float* __restrict__ A, const float* __restrict__ W,
    float* __restrict__ C, const float* __restrict__ aux,
    int M, int N, int K)
{
    __shared__ float As[16][128];
    __shared__ float Bs[16][128];

    int tid = threadIdx.x;
    int bx = blockIdx.x;   // N tile
    int by = blockIdx.y;   // M tile

    const float* Ab = A + (size_t)by * 128 * K;
    const float* Bb = W + (size_t)bx * 128;

    float acc[8][8];
    #pragma unroll
    for (int r = 0; r < 8; r++)
        #pragma unroll
        for (int c = 0; c < 8; c++) acc[r][c] = 0.f;

    int arow = tid >> 2;           // 0..63
    int acol = (tid & 3) << 2;     // 0,4,8,12
    int brow = tid >> 5;           // 0..7
    int bcol = (tid & 31) << 2;    // 0..124
    int tx = tid & 15, ty = tid >> 4;

    for (int k0 = 0; k0 < K; k0 += 16) {
        float4 a0 = *(const float4*)(Ab + (size_t)arow * K + k0 + acol);
        float4 a1 = *(const float4*)(Ab + (size_t)(arow + 64) * K + k0 + acol);
        As[acol + 0][arow] = a0.x; As[acol + 1][arow] = a0.y;
        As[acol + 2][arow] = a0.z; As[acol + 3][arow] = a0.w;
        As[acol + 0][arow + 64] = a1.x; As[acol + 1][arow + 64] = a1.y;
        As[acol + 2][arow + 64] = a1.z; As[acol + 3][arow + 64] = a1.w;

        float4 b0 = *(const float4*)(Bb + (size_t)(k0 + brow) * N + bcol);
        float4 b1 = *(const float4*)(Bb + (size_t)(k0 + brow + 8) * N + bcol);
        *(float4*)&Bs[brow][bcol] = b0;
        *(float4*)&Bs[brow + 8][bcol] = b1;
        __syncthreads();

        #pragma unroll
        for (int k = 0; k < 16; k++) {
            float af[8], bf[8];
            *(float4*)(af)     = *(const float4*)&As[k][ty * 8];
            *(float4*)(af + 4) = *(const float4*)&As[k][ty * 8 + 4];
            *(float4*)(bf)     = *(const float4*)&Bs[k][tx * 8];
            *(float4*)(bf + 4) = *(const float4*)&Bs[k][tx * 8 + 4];
            #pragma unroll
            for (int r = 0; r < 8; r++)
                #pragma unroll
                for (int c = 0; c < 8; c++)
                    acc[r][c] = fmaf(af[r], bf[c], acc[r][c]);
        }
        __syncthreads();
    }

    #pragma unroll
    for (int r = 0; r < 8; r++) {
        size_t row = (size_t)(by * 128 + ty * 8 + r);
        size_t base = row * N + (size_t)bx * 128 + tx * 8;
        #pragma unroll
        for (int cg = 0; cg < 2; cg++) {
            float v[4];
            #pragma unroll
            for (int c = 0; c < 4; c++) {
                float t = acc[r][cg * 4 + c];
                if (MODE == 1) t = silu(t);
                v[c] = t;
            }
            if (MODE == 2 || MODE == 3) {
                float4 av = *(const float4*)(aux + base + cg * 4);
                if (MODE == 2) { v[0]+=av.x; v[1]+=av.y; v[2]+=av.z; v[3]+=av.w; }
                else           { v[0]*=av.x; v[1]*=av.y; v[2]*=av.z; v[3]*=av.w; }
            }
            *(float4*)(C + base + cg * 4) = *(float4*)v;
        }
    }
}

// ---------------- Fused causal silu-attention + head-LN * u ----------------
// grid: (L/64 q-blocks, B*H). 256 threads. Per block: 64 q rows, d=64 full.
// A[i,:] += silu(Q K^T / 8)[i,k] * V[k,:]; then LN over d, * u, store [B,L,D].
#define APAD 68
__global__ __launch_bounds__(256) void attn_kernel(
    const float* __restrict__ qkuv, const float* __restrict__ nag,
    const float* __restrict__ nab, float* __restrict__ abuf)
{
    extern __shared__ float sm[];
    float* Qt = sm;                 // [64][APAD]  transposed: Qt[d][i]
    float* Kt = Qt + 64 * APAD;     // [64][APAD]  Kt[d][j]
    float* Vs = Kt + 64 * APAD;     // [64][APAD]  Vs[k][c]
    float* Ss = Vs + 64 * APAD;     // [64][APAD]  Ss[k][i] (S transposed), reused for A
    __shared__ float mu_s[64];
    __shared__ float rs_s[64];

    int qb = blockIdx.x;            // 0..31
    int bh = blockIdx.y;            // 0..31
    int b = bh / HH, h = bh % HH;
    int tid = threadIdx.x;
    int tx = tid & 15, ty = tid >> 4;

    const size_t rowstride = 4 * DD;
    const float* base = qkuv + (size_t)(b * LL) * rowstride + h * HD;

    // load Q tile (rows qb*64..+63), transposed into Qt[d][i]
    #pragma unroll
    for (int t = 0; t < 4; t++) {
        int idx = tid + t * 256;
        int r = idx >> 4;               // 0..63
        int c4 = (idx & 15) << 2;       // 0..60
        float4 qv = *(const float4*)(base + (size_t)(qb * 64 + r) * rowstride + c4);
        Qt[(c4 + 0) * APAD + r] = qv.x;
        Qt[(c4 + 1) * APAD + r] = qv.y;
        Qt[(c4 + 2) * APAD + r] = qv.z;
        Qt[(c4 + 3) * APAD + r] = qv.w;
    }

    float accA[4][4];
    #pragma unroll
    for (int r = 0; r < 4; r++)
        #pragma unroll
        for (int c = 0; c < 4; c++) accA[r][c] = 0.f;

    for (int kb = 0; kb <= qb; kb++) {
        __syncthreads();   // previous iter done with Kt/Vs/Ss; Q visible on first iter
        // load K (transposed) and V tiles
        #pragma unroll
        for (int t = 0; t < 4; t++) {
            int idx = tid + t * 256;
            int r = idx >> 4;
            int c4 = (idx & 15) << 2;
            const float* krow = base + DD + (size_t)(kb * 64 + r) * rowstride;
            float4 kv = *(const float4*)(krow + c4);
            Kt[(c4 + 0) * APAD + r] = kv.x;
            Kt[(c4 + 1) * APAD + r] = kv.y;
            Kt[(c4 + 2) * APAD + r] = kv.z;
            Kt[(c4 + 3) * APAD + r] = kv.w;
            const float* vrow = base + 2 * DD + (size_t)(kb * 64 + r) * rowstride;
            *(float4*)&Vs[r * APAD + c4] = *(const float4*)(vrow + c4);
        }
        __syncthreads();

        // S = Q @ K^T
        float sacc[4][4];
        #pragma unroll
        for (int r = 0; r < 4; r++)
            #pragma unroll
            for (int c = 0; c < 4; c++) sacc[r][c] = 0.f;
        #pragma unroll
        for (int dd = 0; dd < 64; dd++) {
            float4 qv = *(const float4*)&Qt[dd * APAD + ty * 4];
            float4 kv = *(const float4*)&Kt[dd * APAD + tx * 4];
            float qf[4] = {qv.x, qv.y, qv.z, qv.w};
            float kf[4] = {kv.x, kv.y, kv.z, kv.w};
            #pragma unroll
            for (int r = 0; r < 4; r++)
                #pragma unroll
                for (int c = 0; c < 4; c++)
                    sacc[r][c] = fmaf(qf[r], kf[c], sacc[r][c]);
        }
        // silu, scale, causal mask; write transposed Ss[j][i]
        bool diag = (kb == qb);
        #pragma unroll
        for (int r = 0; r < 4; r++) {
            int gi = ty * 4 + r;
            #pragma unroll
            for (int c = 0; c < 4; c++) {
                int gj = tx * 4 + c;
                float s = sacc[r][c] * 0.125f;
                s = silu(s);
                if (diag && gj > gi) s = 0.f;
                Ss[gj * APAD + gi] = s;
            }
        }
        __syncthreads();

        // A += S @ V
        #pragma unroll
        for (int kk = 0; kk < 64; kk++) {
            float4 sv = *(const float4*)&Ss[kk * APAD + ty * 4];
            float4 vv = *(const float4*)&Vs[kk * APAD + tx * 4];
            float sf[4] = {sv.x, sv.y, sv.z, sv.w};
            float vf[4] = {vv.x, vv.y, vv.z, vv.w};
            #pragma unroll
            for (int r = 0; r < 4; r++)
                #pragma unroll
                for (int c = 0; c < 4; c++)
                    accA[r][c] = fmaf(sf[r], vf[c], accA[r][c]);
        }
    }

    // epilogue: LN over d=64 per row, * u, store into [B,L,D]
    __syncthreads();
    #pragma unroll
    for (int r = 0; r < 4; r++)
        #pragma unroll
        for (int c = 0; c < 4; c++)
            Ss[(ty * 4 + r) * APAD + (tx * 4 + c)] = accA[r][c];
    __syncthreads();
    if (tid < 64) {
        float s = 0.f, s2 = 0.f;
        #pragma unroll
        for (int c = 0; c < 64; c++) {
            float v = Ss[tid * APAD + c];
            s += v; s2 += v * v;
        }
        float mu = s * (1.0f / 64.0f);
        float var = s2 * (1.0f / 64.0f) - mu * mu;
        mu_s[tid] = mu;
        rs_s[tid] = rsqrtf(var + 1e-5f);
    }
    __syncthreads();

    #pragma unroll
    for (int r = 0; r < 4; r++) {
        int i = ty * 4 + r;
        int l = qb * 64 + i;
        float mu = mu_s[i], rstd = rs_s[i];
        const float* urow = base + 3 * DD + (size_t)l * rowstride + tx * 4;
        float4 uv = *(const float4*)urow;
        float uf[4] = {uv.x, uv.y, uv.z, uv.w};
        float v[4];
        #pragma unroll
        for (int c = 0; c < 4; c++) {
            int col = tx * 4 + c;
            float t = (accA[r][c] - mu) * rstd * nag[col] + nab[col];
            v[c] = t * uf[c];
        }
        *(float4*)(abuf + (size_t)(b * LL + l) * DD + h * HD + tx * 4) = *(float4*)v;
    }
}

// ---------------- host ------------------------------------------------------
extern "C" void kernel_launch(void* const* d_in, const int* in_sizes, int n_in,
                              void* d_out, int out_size)
{
    const float* x      = (const float*)d_in[0];
    // d_in[1] = attn_mask (unused; causality handled analytically)
    const float* w_qkuv = (const float*)d_in[2];
    const float* w_out  = (const float*)d_in[3];
    const float* w1     = (const float*)d_in[4];
    const float* w2     = (const float*)d_in[5];
    const float* w3     = (const float*)d_in[6];
    const float* ln1_g  = (const float*)d_in[7];
    const float* ln1_b  = (const float*)d_in[8];
    const float* ln2_g  = (const float*)d_in[9];
    const float* ln2_b  = (const float*)d_in[10];
    const float* na_g   = (const float*)d_in[11];
    const float* na_b   = (const float*)d_in[12];
    float* out = (float*)d_out;

    float *xn, *qkuv, *abuf, *x1, *xn2, *h1, *hbuf;
    cudaGetSymbolAddress((void**)&xn,   g_xn);
    cudaGetSymbolAddress((void**)&qkuv, g_qkuv);
    cudaGetSymbolAddress((void**)&abuf, g_a);
    cudaGetSymbolAddress((void**)&x1,   g_x1);
    cudaGetSymbolAddress((void**)&xn2,  g_xn2);
    cudaGetSymbolAddress((void**)&h1,   g_h1);
    cudaGetSymbolAddress((void**)&hbuf, g_h);

    const int ATTN_SMEM = 4 * 64 * APAD * (int)sizeof(float);  // 69632 B
    cudaFuncSetAttribute(attn_kernel, cudaFuncAttributeMaxDynamicSharedMemorySize, ATTN_SMEM);

    dim3 blk(256);

    // 1. LN1
    ln_kernel<<<MROWS, blk>>>(x, ln1_g, ln1_b, xn);
    // 2. qkuv = silu(xn @ w_qkuv)   [4096 x 4096], K=1024
    sgemm_kernel<1><<<dim3(4 * DD / 128, MROWS / 128), blk>>>(xn, w_qkuv, qkuv, nullptr, MROWS, 4 * DD, DD);
    // 3. fused attention + headLN*u -> abuf [B,L,D]
    attn_kernel<<<dim3(LL / 64, BB * HH), blk, ATTN_SMEM>>>(qkuv, na_g, na_b, abuf);
    // 4. x1 = x + abuf @ w_out      [4096 x 1024], K=1024
    sgemm_kernel<2><<<dim3(DD / 128, MROWS / 128), blk>>>(abuf, w_out, x1, x, MROWS, DD, DD);
    // 5. LN2
    ln_kernel<<<MROWS, blk>>>(x1, ln2_g, ln2_b, xn2);
    // 6. h1 = silu(xn2 @ w1)        [4096 x 4096], K=1024
    sgemm_kernel<1><<<dim3(FF / 128, MROWS / 128), blk>>>(xn2, w1, h1, nullptr, MROWS, FF, DD);
    // 7. h = (xn2 @ w3) * h1        [4096 x 4096], K=1024
    sgemm_kernel<3><<<dim3(FF / 128, MROWS / 128), blk>>>(xn2, w3, hbuf, h1, MROWS, FF, DD);
    // 8. out = x1 + h @ w2          [4096 x 1024], K=4096
    sgemm_kernel<2><<<dim3(DD / 128, MROWS / 128), blk>>>(hbuf, w2, out, x1, MROWS, DD, FF);
}

// round 3
// speedup vs baseline: 2.0263x; 2.0263x over previous
#include <cuda_runtime.h>
#include <cuda_bf16.h>
#include <cstdint>
#include <math.h>

#define BB 2
#define LL 2048
#define DD 1024
#define HH 16
#define HD 64
#define FF 4096
#define MROWS (BB*LL)   // 4096

// ---------------- scratch (device globals) ---------------------------------
__device__ __nv_bfloat16 g_xn_hi [MROWS * DD];
__device__ __nv_bfloat16 g_xn_lo [MROWS * DD];
__device__ float         g_qkuv  [MROWS * 4 * DD];
__device__ __nv_bfloat16 g_a_hi  [MROWS * DD];
__device__ __nv_bfloat16 g_a_lo  [MROWS * DD];
__device__ float         g_x1    [MROWS * DD];
__device__ __nv_bfloat16 g_xn2_hi[MROWS * DD];
__device__ __nv_bfloat16 g_xn2_lo[MROWS * DD];
__device__ float         g_h1    [MROWS * FF];
__device__ __nv_bfloat16 g_h_hi  [MROWS * FF];
__device__ __nv_bfloat16 g_h_lo  [MROWS * FF];
// transposed + split weights: [N, K] K-major
__device__ __nv_bfloat16 g_wqkuv_hi[4 * DD * DD];
__device__ __nv_bfloat16 g_wqkuv_lo[4 * DD * DD];
__device__ __nv_bfloat16 g_wout_hi [DD * DD];
__device__ __nv_bfloat16 g_wout_lo [DD * DD];
__device__ __nv_bfloat16 g_w1_hi   [DD * FF];
__device__ __nv_bfloat16 g_w1_lo   [DD * FF];
__device__ __nv_bfloat16 g_w3_hi   [DD * FF];
__device__ __nv_bfloat16 g_w3_lo   [DD * FF];
__device__ __nv_bfloat16 g_w2_hi   [FF * DD];
__device__ __nv_bfloat16 g_w2_lo   [FF * DD];

__device__ __forceinline__ float silu(float x) { return x / (1.0f + expf(-x)); }

__device__ __forceinline__ uint32_t smem_u32(const void* p) {
    uint32_t a;
    asm("{ .reg .u64 t; cvta.to.shared.u64 t, %1; cvt.u32.u64 %0, t; }" : "=r"(a) : "l"(p));
    return a;
}
__device__ __forceinline__ void cp16(uint32_t s, const void* g) {
    asm volatile("cp.async.cg.shared.global [%0], [%1], 16;" :: "r"(s), "l"(g) : "memory");
}
__device__ __forceinline__ void bf_split(float v, __nv_bfloat16& h, __nv_bfloat16& l) {
    h = __float2bfloat16(v);
    l = __float2bfloat16(v - __bfloat162float(h));
}
__device__ __forceinline__ uint32_t pack2(__nv_bfloat16 a, __nv_bfloat16 b) {
    return (uint32_t)__bfloat16_as_ushort(a) | ((uint32_t)__bfloat16_as_ushort(b) << 16);
}
__device__ __forceinline__ void ldsm4(uint32_t* r, uint32_t a) {
    asm volatile("ldmatrix.sync.aligned.m8n8.x4.shared.b16 {%0,%1,%2,%3}, [%4];"
        : "=r"(r[0]), "=r"(r[1]), "=r"(r[2]), "=r"(r[3]) : "r"(a));
}
__device__ __forceinline__ void mma16816(float* c, const uint32_t* a, uint32_t b0, uint32_t b1) {
    asm volatile(
        "mma.sync.aligned.m16n8k16.row.col.f32.bf16.bf16.f32 "
        "{%0,%1,%2,%3}, {%4,%5,%6,%7}, {%8,%9}, {%0,%1,%2,%3};"
        : "+f"(c[0]), "+f"(c[1]), "+f"(c[2]), "+f"(c[3])
        : "r"(a[0]), "r"(a[1]), "r"(a[2]), "r"(a[3]), "r"(b0), "r"(b1));
}

// ---------------- weight transpose + split:  w[K,N] -> wt_hi/lo[N,K] -------
__global__ __launch_bounds__(256) void wsplit_kernel(
    const float* __restrict__ w, __nv_bfloat16* __restrict__ whi,
    __nv_bfloat16* __restrict__ wlo, int K, int N)
{
    __shared__ float t[32][33];
    int n0 = blockIdx.x * 32, k0 = blockIdx.y * 32;
    int tx = threadIdx.x & 31, ty = threadIdx.x >> 5;
    #pragma unroll
    for (int j = 0; j < 4; j++)
        t[ty + j * 8][tx] = w[(size_t)(k0 + ty + j * 8) * N + n0 + tx];
    __syncthreads();
    #pragma unroll
    for (int j = 0; j < 4; j++) {
        int nn = ty + j * 8;
        float v = t[tx][nn];
        __nv_bfloat16 h, l; bf_split(v, h, l);
        size_t o = (size_t)(n0 + nn) * K + k0 + tx;
        whi[o] = h; wlo[o] = l;
    }
}

// ---------------- LayerNorm -> split bf16 -----------------------------------
__global__ __launch_bounds__(256) void ln_split_kernel(
    const float* __restrict__ x, const float* __restrict__ g,
    const float* __restrict__ b, __nv_bfloat16* __restrict__ oh,
    __nv_bfloat16* __restrict__ ol)
{
    int row = blockIdx.x;
    const float* xr = x + (size_t)row * DD;
    float s = 0.f, s2 = 0.f;
    for (int i = threadIdx.x; i < DD; i += 256) {
        float v = xr[i]; s += v; s2 += v * v;
    }
    __shared__ float red[8], red2[8], stats[2];
    for (int off = 16; off > 0; off >>= 1) {
        s  += __shfl_down_sync(0xffffffffu, s,  off);
        s2 += __shfl_down_sync(0xffffffffu, s2, off);
    }
    int wid = threadIdx.x >> 5, lid = threadIdx.x & 31;
    if (lid == 0) { red[wid] = s; red2[wid] = s2; }
    __syncthreads();
    if (threadIdx.x == 0) {
        float ts = 0.f, ts2 = 0.f;
        for (int i = 0; i < 8; i++) { ts += red[i]; ts2 += red2[i]; }
        float mu = ts * (1.0f / DD);
        float var = ts2 * (1.0f / DD) - mu * mu;
        stats[0] = mu; stats[1] = rsqrtf(var + 1e-5f);
    }
    __syncthreads();
    float mu = stats[0], rstd = stats[1];
    for (int i = threadIdx.x; i < DD; i += 256) {
        float v = (xr[i] - mu) * rstd * g[i] + b[i];
        __nv_bfloat16 h, l; bf_split(v, h, l);
        oh[(size_t)row * DD + i] = h;
        ol[(size_t)row * DD + i] = l;
    }
}

// ---------------- mma.sync split-bf16 GEMM -----------------------------------
// D[m,n] = sum_k A[m,k]*B[n,k], A=Ahi+Alo, B=Bhi+Blo (3 of 4 split terms)
// MODE 0: Cf = silu(d); MODE 1: Cf = d + aux; MODE 2: (d*aux) -> Chi/Clo
// Tile: BM=BN=128, BK=64. 256 threads, warp grid 2(M) x 4(N), warp tile 64x32.
#define SPAD 72                     // bf16 padded row stride (144 B)
#define TEN_BYTES (128 * SPAD * 2)  // 18432 per tensor
#define STAGE_BYTES (4 * TEN_BYTES) // 73728
#define GSTAGES 2
#define GEMM_SMEM (GSTAGES * STAGE_BYTES)

template <int MODE>
__global__ __launch_bounds__(256, 1) void gemm_mma(
    const __nv_bfloat16* __restrict__ Ahi, const __nv_bfloat16* __restrict__ Alo,
    const __nv_bfloat16* __restrict__ Bhi, const __nv_bfloat16* __restrict__ Blo,
    float* __restrict__ Cf, const float* __restrict__ aux,
    __nv_bfloat16* __restrict__ Chi, __nv_bfloat16* __restrict__ Clo,
    int M, int N, int K)
{
    extern __shared__ char smem[];
    const uint32_t sbase = smem_u32(smem);
    const int tid = threadIdx.x, lane = tid & 31, wid = tid >> 5;
    const int wm = wid & 1, wn = wid >> 1;
    const int bx = blockIdx.x, by = blockIdx.y;

    const size_t rowbytes = (size_t)K * 2;
    const char* base[4] = {
        (const char*)(Ahi + (size_t)by * 128 * K),
        (const char*)(Alo + (size_t)by * 128 * K),
        (const char*)(Bhi + (size_t)bx * 128 * K),
        (const char*)(Blo + (size_t)bx * 128 * K)
    };

    // per-thread smem addr templates for ldmatrix
    const uint32_t aRowOff = (uint32_t)((wm * 64 + (lane & 15)) * (SPAD * 2) + (lane >> 4) * 16);
    const int bg = lane >> 3;  // matrix id 0..3
    const uint32_t bRowOff = (uint32_t)((wn * 32 + (bg >> 1) * 8 + (lane & 7)) * (SPAD * 2) + (bg & 1) * 16);

    auto load_slab = [&](int ks, int st) {
        uint32_t stg = sbase + (uint32_t)st * STAGE_BYTES;
        size_t koff = (size_t)ks * 128;   // 64 bf16
        #pragma unroll
        for (int i = 0; i < 16; i++) {
            int c = tid + i * 256;
            int tn = c >> 10;
            int rr = (c >> 3) & 127;
            int ck = (c & 7) * 16;
            cp16(stg + (uint32_t)(tn * TEN_BYTES + rr * (SPAD * 2) + ck),
                 base[tn] + (size_t)rr * rowbytes + koff + ck);
        }
        asm volatile("cp.async.commit_group;" ::: "memory");
    };

    float acc[4][4][4];
    #pragma unroll
    for (int mt = 0; mt < 4; mt++)
        #pragma unroll
        for (int nt = 0; nt < 4; nt++)
            #pragma unroll
            for (int j = 0; j < 4; j++) acc[mt][nt][j] = 0.f;

    const int ns = K >> 6;
    load_slab(0, 0);
    if (ns > 1) load_slab(1, 1);

    for (int i = 0; i < ns; i++) {
        if (i + 1 < ns) asm volatile("cp.async.wait_group 1;" ::: "memory");
        else            asm volatile("cp.async.wait_group 0;" ::: "memory");
        __syncthreads();

        uint32_t stg = sbase + (uint32_t)(i % GSTAGES) * STAGE_BYTES;
        uint32_t aHiB = stg + aRowOff;
        uint32_t aLoB = stg + TEN_BYTES + aRowOff;
        uint32_t bHiB = stg + 2 * TEN_BYTES + bRowOff;
        uint32_t bLoB = stg + 3 * TEN_BYTES + bRowOff;

        #pragma unroll
        for (int ks = 0; ks < 4; ks++) {
            uint32_t ah[4][4], al[4][4], bh[2][4], bl[2][4];
            #pragma unroll
            for (int mt = 0; mt < 4; mt++) {
                uint32_t o = (uint32_t)(mt * 16 * (SPAD * 2) + ks * 32);
                ldsm4(ah[mt], aHiB + o);
                ldsm4(al[mt], aLoB + o);
            }
            #pragma unroll
            for (int p = 0; p < 2; p++) {
                uint32_t o = (uint32_t)(p * 16 * (SPAD * 2) + ks * 32);
                ldsm4(bh[p], bHiB + o);
                ldsm4(bl[p], bLoB + o);
            }
            #pragma unroll
            for (int mt = 0; mt < 4; mt++) {
                #pragma unroll
                for (int nt = 0; nt < 4; nt++) {
                    int p = nt >> 1, o = (nt & 1) * 2;
                    mma16816(acc[mt][nt], ah[mt], bh[p][o], bh[p][o + 1]);
                    mma16816(acc[mt][nt], ah[mt], bl[p][o], bl[p][o + 1]);
                    mma16816(acc[mt][nt], al[mt], bh[p][o], bh[p][o + 1]);
                }
            }
        }
        __syncthreads();
        if (i + 2 < ns) load_slab(i + 2, (i + 2) % GSTAGES);
    }

    // ----- epilogue ----------------------------------------------------------
    const int groupID = lane >> 2, tid4 = lane & 3;
    #pragma unroll
    for (int mt = 0; mt < 4; mt++) {
        int r0 = by * 128 + wm * 64 + mt * 16 + groupID;
        #pragma unroll
        for (int nt = 0; nt < 4; nt++) {
            int cg = bx * 128 + wn * 32 + nt * 8 + tid4 * 2;
            float* a = acc[mt][nt];
            #pragma unroll
            for (int half = 0; half < 2; half++) {
                size_t off = (size_t)(r0 + half * 8) * N + cg;
                float v0 = a[half * 2 + 0], v1 = a[half * 2 + 1];
                if (MODE == 0) {
                    float2 o; o.x = silu(v0); o.y = silu(v1);
                    *(float2*)(Cf + off) = o;
                } else if (MODE == 1) {
                    float2 ax = *(const float2*)(aux + off);
                    float2 o; o.x = v0 + ax.x; o.y = v1 + ax.y;
                    *(float2*)(Cf + off) = o;
                } else {
                    float2 ax = *(const float2*)(aux + off);
                    float t0 = v0 * ax.x, t1 = v1 * ax.y;
                    __nv_bfloat16 h0, l0, h1, l1;
                    bf_split(t0, h0, l0);
                    bf_split(t1, h1, l1);
                    *(uint32_t*)(Chi + off) = pack2(h0, h1);
                    *(uint32_t*)(Clo + off) = pack2(l0, l1);
                }
            }
        }
    }
}

// ---------------- Fused causal silu-attention + head-LN * u (FFMA) ---------
#define APAD 68
__global__ __launch_bounds__(256) void attn_kernel(
    const float* __restrict__ qkuv, const float* __restrict__ nag,
    const float* __restrict__ nab, __nv_bfloat16* __restrict__ ahi,
    __nv_bfloat16* __restrict__ alo)
{
    extern __shared__ float sm[];
    float* Qt = sm;
    float* Kt = Qt + 64 * APAD;
    float* Vs = Kt + 64 * APAD;
    float* Ss = Vs + 64 * APAD;
    __shared__ float mu_s[64];
    __shared__ float rs_s[64];

    int qb = blockIdx.x;
    int bh = blockIdx.y;
    int b = bh / HH, h = bh % HH;
    int tid = threadIdx.x;
    int tx = tid & 15, ty = tid >> 4;

    const size_t rowstride = 4 * DD;
    const float* base = qkuv + (size_t)(b * LL) * rowstride + h * HD;

    #pragma unroll
    for (int t = 0; t < 4; t++) {
        int idx = tid + t * 256;
        int r = idx >> 4;
        int c4 = (idx & 15) << 2;
        float4 qv = *(const float4*)(base + (size_t)(qb * 64 + r) * rowstride + c4);
        Qt[(c4 + 0) * APAD + r] = qv.x;
        Qt[(c4 + 1) * APAD + r] = qv.y;
        Qt[(c4 + 2) * APAD + r] = qv.z;
        Qt[(c4 + 3) * APAD + r] = qv.w;
    }

    float accA[4][4];
    #pragma unroll
    for (int r = 0; r < 4; r++)
        #pragma unroll
        for (int c = 0; c < 4; c++) accA[r][c] = 0.f;

    for (int kb = 0; kb <= qb; kb++) {
        __syncthreads();
        #pragma unroll
        for (int t = 0; t < 4; t++) {
            int idx = tid + t * 256;
            int r = idx >> 4;
            int c4 = (idx & 15) << 2;
            const float* krow = base + DD + (size_t)(kb * 64 + r) * rowstride;
            float4 kv = *(const float4*)(krow + c4);
            Kt[(c4 + 0) * APAD + r] = kv.x;
            Kt[(c4 + 1) * APAD + r] = kv.y;
            Kt[(c4 + 2) * APAD + r] = kv.z;
            Kt[(c4 + 3) * APAD + r] = kv.w;
            const float* vrow = base + 2 * DD + (size_t)(kb * 64 + r) * rowstride;
            *(float4*)&Vs[r * APAD + c4] = *(const float4*)(vrow + c4);
        }
        __syncthreads();

        float sacc[4][4];
        #pragma unroll
        for (int r = 0; r < 4; r++)
            #pragma unroll
            for (int c = 0; c < 4; c++) sacc[r][c] = 0.f;
        #pragma unroll
        for (int dd = 0; dd < 64; dd++) {
            float4 qv = *(const float4*)&Qt[dd * APAD + ty * 4];
            float4 kv = *(const float4*)&Kt[dd * APAD + tx * 4];
            float qf[4] = {qv.x, qv.y, qv.z, qv.w};
            float kf[4] = {kv.x, kv.y, kv.z, kv.w};
            #pragma unroll
            for (int r = 0; r < 4; r++)
                #pragma unroll
                for (int c = 0; c < 4; c++)
                    sacc[r][c] = fmaf(qf[r], kf[c], sacc[r][c]);
        }
        bool diag = (kb == qb);
        #pragma unroll
        for (int r = 0; r < 4; r++) {
            int gi = ty * 4 + r;
            #pragma unroll
            for (int c = 0; c < 4; c++) {
                int gj = tx * 4 + c;
                float s = sacc[r][c] * 0.125f;
                s = silu(s);
                if (diag && gj > gi) s = 0.f;
                Ss[gj * APAD + gi] = s;
            }
        }
        __syncthreads();

        #pragma unroll
        for (int kk = 0; kk < 64; kk++) {
            float4 sv = *(const float4*)&Ss[kk * APAD + ty * 4];
            float4 vv = *(const float4*)&Vs[kk * APAD + tx * 4];
            float sf[4] = {sv.x, sv.y, sv.z, sv.w};
            float vf[4] = {vv.x, vv.y, vv.z, vv.w};
            #pragma unroll
            for (int r = 0; r < 4; r++)
                #pragma unroll
                for (int c = 0; c < 4; c++)
                    accA[r][c] = fmaf(sf[r], vf[c], accA[r][c]);
        }
    }

    __syncthreads();
    #pragma unroll
    for (int r = 0; r < 4; r++)
        #pragma unroll
        for (int c = 0; c < 4; c++)
            Ss[(ty * 4 + r) * APAD + (tx * 4 + c)] = accA[r][c];
    __syncthreads();
    if (tid < 64) {
        float s = 0.f, s2 = 0.f;
        #pragma unroll
        for (int c = 0; c < 64; c++) {
            float v = Ss[tid * APAD + c];
            s += v; s2 += v * v;
        }
        float mu = s * (1.0f / 64.0f);
        float var = s2 * (1.0f / 64.0f) - mu * mu;
        mu_s[tid] = mu;
        rs_s[tid] = rsqrtf(var + 1e-5f);
    }
    __syncthreads();

    #pragma unroll
    for (int r = 0; r < 4; r++) {
        int i = ty * 4 + r;
        int l = qb * 64 + i;
        float mu = mu_s[i], rstd = rs_s[i];
        const float* urow = base + 3 * DD + (size_t)l * rowstride + tx * 4;
        float4 uv = *(const float4*)urow;
        float uf[4] = {uv.x, uv.y, uv.z, uv.w};
        __nv_bfloat16 hv[4], lv[4];
        #pragma unroll
        for (int c = 0; c < 4; c++) {
            int col = tx * 4 + c;
            float t = (accA[r][c] - mu) * rstd * nag[col] + nab[col];
            bf_split(t * uf[c], hv[c], lv[c]);
        }
        size_t off = (size_t)(b * LL + l) * DD + h * HD + tx * 4;
        *(uint2*)(ahi + off) = make_uint2(pack2(hv[0], hv[1]), pack2(hv[2], hv[3]));
        *(uint2*)(alo + off) = make_uint2(pack2(lv[0], lv[1]), pack2(lv[2], lv[3]));
    }
}

// ---------------- host -------------------------------------------------------
extern "C" void kernel_launch(void* const* d_in, const int* in_sizes, int n_in,
                              void* d_out, int out_size)
{
    const float* x      = (const float*)d_in[0];
    const float* w_qkuv = (const float*)d_in[2];
    const float* w_out  = (const float*)d_in[3];
    const float* w1     = (const float*)d_in[4];
    const float* w2     = (const float*)d_in[5];
    const float* w3     = (const float*)d_in[6];
    const float* ln1_g  = (const float*)d_in[7];
    const float* ln1_b  = (const float*)d_in[8];
    const float* ln2_g  = (const float*)d_in[9];
    const float* ln2_b  = (const float*)d_in[10];
    const float* na_g   = (const float*)d_in[11];
    const float* na_b   = (const float*)d_in[12];
    float* out = (float*)d_out;

    __nv_bfloat16 *xnh, *xnl, *ah, *al, *xn2h, *xn2l, *hh, *hl;
    __nv_bfloat16 *wqh, *wql, *woh, *wol, *w1h, *w1l, *w3h, *w3l, *w2h, *w2l;
    float *qkuv, *x1, *h1;
    cudaGetSymbolAddress((void**)&xnh,  g_xn_hi);  cudaGetSymbolAddress((void**)&xnl,  g_xn_lo);
    cudaGetSymbolAddress((void**)&qkuv, g_qkuv);
    cudaGetSymbolAddress((void**)&ah,   g_a_hi);   cudaGetSymbolAddress((void**)&al,   g_a_lo);
    cudaGetSymbolAddress((void**)&x1,   g_x1);
    cudaGetSymbolAddress((void**)&xn2h, g_xn2_hi); cudaGetSymbolAddress((void**)&xn2l, g_xn2_lo);
    cudaGetSymbolAddress((void**)&h1,   g_h1);
    cudaGetSymbolAddress((void**)&hh,   g_h_hi);   cudaGetSymbolAddress((void**)&hl,   g_h_lo);
    cudaGetSymbolAddress((void**)&wqh,  g_wqkuv_hi); cudaGetSymbolAddress((void**)&wql, g_wqkuv_lo);
    cudaGetSymbolAddress((void**)&woh,  g_wout_hi);  cudaGetSymbolAddress((void**)&wol, g_wout_lo);
    cudaGetSymbolAddress((void**)&w1h,  g_w1_hi);    cudaGetSymbolAddress((void**)&w1l, g_w1_lo);
    cudaGetSymbolAddress((void**)&w3h,  g_w3_hi);    cudaGetSymbolAddress((void**)&w3l, g_w3_lo);
    cudaGetSymbolAddress((void**)&w2h,  g_w2_hi);    cudaGetSymbolAddress((void**)&w2l, g_w2_lo);

    cudaFuncSetAttribute(gemm_mma<0>, cudaFuncAttributeMaxDynamicSharedMemorySize, GEMM_SMEM);
    cudaFuncSetAttribute(gemm_mma<1>, cudaFuncAttributeMaxDynamicSharedMemorySize, GEMM_SMEM);
    cudaFuncSetAttribute(gemm_mma<2>, cudaFuncAttributeMaxDynamicSharedMemorySize, GEMM_SMEM);
    const int ATTN_SMEM = 4 * 64 * APAD * (int)sizeof(float);
    cudaFuncSetAttribute(attn_kernel, cudaFuncAttributeMaxDynamicSharedMemorySize, ATTN_SMEM);

    dim3 blk(256);

    // 0. weight transpose + split (w[K,N] -> [N,K] hi/lo)
    wsplit_kernel<<<dim3(4 * DD / 32, DD / 32), blk>>>(w_qkuv, wqh, wql, DD, 4 * DD);
    wsplit_kernel<<<dim3(DD / 32, DD / 32),     blk>>>(w_out,  woh, wol, DD, DD);
    wsplit_kernel<<<dim3(FF / 32, DD / 32),     blk>>>(w1,     w1h, w1l, DD, FF);
    wsplit_kernel<<<dim3(FF / 32, DD / 32),     blk>>>(w3,     w3h, w3l, DD, FF);
    wsplit_kernel<<<dim3(DD / 32, FF / 32),     blk>>>(w2,     w2h, w2l, FF, DD);

    // 1. LN1 -> split
    ln_split_kernel<<<MROWS, blk>>>(x, ln1_g, ln1_b, xnh, xnl);
    // 2. qkuv = silu(xn @ w_qkuv)
    gemm_mma<0><<<dim3(4 * DD / 128, MROWS / 128), blk, GEMM_SMEM>>>(
        xnh, xnl, wqh, wql, qkuv, nullptr, nullptr, nullptr, MROWS, 4 * DD, DD);
    // 3. attention -> a hi/lo
    attn_kernel<<<dim3(LL / 64, BB * HH), blk, ATTN_SMEM>>>(qkuv, na_g, na_b, ah, al);
    // 4. x1 = x + a @ w_out
    gemm_mma<1><<<dim3(DD / 128, MROWS / 128), blk, GEMM_SMEM>>>(
        ah, al, woh, wol, x1, x, nullptr, nullptr, MROWS, DD, DD);
    // 5. LN2 -> split
    ln_split_kernel<<<MROWS, blk>>>(x1, ln2_g, ln2_b, xn2h, xn2l);
    // 6. h1 = silu(xn2 @ w1)
    gemm_mma<0><<<dim3(FF / 128, MROWS / 128), blk, GEMM_SMEM>>>(
        xn2h, xn2l, w1h, w1l, h1, nullptr, nullptr, nullptr, MROWS, FF, DD);
    // 7. h = (xn2 @ w3) * h1 -> hi/lo
    gemm_mma<2><<<dim3(FF / 128, MROWS / 128), blk, GEMM_SMEM>>>(
        xn2h, xn2l, w3h, w3l, nullptr, h1, hh, hl, MROWS, FF, DD);
    // 8. out = x1 + h @ w2
    gemm_mma<1><<<dim3(DD / 128, MROWS / 128), blk, GEMM_SMEM>>>(
        hh, hl, w2h, w2l, out, x1, nullptr, nullptr, MROWS, DD, FF);
}

// round 4
// speedup vs baseline: 2.4915x; 1.2296x over previous
#include <cuda_runtime.h>
#include <cuda_bf16.h>
#include <cstdint>
#include <math.h>

#define BB 2
#define LL 2048
#define DD 1024
#define HH 16
#define HD 64
#define FF 4096
#define MROWS (BB*LL)   // 4096

// ---------------- scratch (device globals) ---------------------------------
__device__ __nv_bfloat16 g_xn_hi [MROWS * DD];
__device__ __nv_bfloat16 g_xn_lo [MROWS * DD];
__device__ float         g_qkuv  [MROWS * 4 * DD];
__device__ __nv_bfloat16 g_a_hi  [MROWS * DD];
__device__ __nv_bfloat16 g_a_lo  [MROWS * DD];
__device__ float         g_x1    [MROWS * DD];
__device__ __nv_bfloat16 g_xn2_hi[MROWS * DD];
__device__ __nv_bfloat16 g_xn2_lo[MROWS * DD];
__device__ float         g_h1    [MROWS * FF];
__device__ __nv_bfloat16 g_h_hi  [MROWS * FF];
__device__ __nv_bfloat16 g_h_lo  [MROWS * FF];
// transposed + split weights: [N, K] K-major
__device__ __nv_bfloat16 g_wqkuv_hi[4 * DD * DD];
__device__ __nv_bfloat16 g_wqkuv_lo[4 * DD * DD];
__device__ __nv_bfloat16 g_wout_hi [DD * DD];
__device__ __nv_bfloat16 g_wout_lo [DD * DD];
__device__ __nv_bfloat16 g_w1_hi   [DD * FF];
__device__ __nv_bfloat16 g_w1_lo   [DD * FF];
__device__ __nv_bfloat16 g_w3_hi   [DD * FF];
__device__ __nv_bfloat16 g_w3_lo   [DD * FF];
__device__ __nv_bfloat16 g_w2_hi   [FF * DD];
__device__ __nv_bfloat16 g_w2_lo   [FF * DD];

__device__ __forceinline__ float silu(float x) {
    return __fdividef(x, 1.0f + __expf(-x));
}

__device__ __forceinline__ uint32_t smem_u32(const void* p) {
    uint32_t a;
    asm("{ .reg .u64 t; cvta.to.shared.u64 t, %1; cvt.u32.u64 %0, t; }" : "=r"(a) : "l"(p));
    return a;
}
__device__ __forceinline__ void cp16(uint32_t s, const void* g) {
    asm volatile("cp.async.cg.shared.global [%0], [%1], 16;" :: "r"(s), "l"(g) : "memory");
}
__device__ __forceinline__ void bf_split(float v, __nv_bfloat16& h, __nv_bfloat16& l) {
    h = __float2bfloat16(v);
    l = __float2bfloat16(v - __bfloat162float(h));
}
__device__ __forceinline__ uint32_t pack2(__nv_bfloat16 a, __nv_bfloat16 b) {
    return (uint32_t)__bfloat16_as_ushort(a) | ((uint32_t)__bfloat16_as_ushort(b) << 16);
}
__device__ __forceinline__ void ldsm4(uint32_t* r, uint32_t a) {
    asm volatile("ldmatrix.sync.aligned.m8n8.x4.shared.b16 {%0,%1,%2,%3}, [%4];"
        : "=r"(r[0]), "=r"(r[1]), "=r"(r[2]), "=r"(r[3]) : "r"(a));
}
__device__ __forceinline__ void mma16816(float* c, const uint32_t* a, uint32_t b0, uint32_t b1) {
    asm volatile(
        "mma.sync.aligned.m16n8k16.row.col.f32.bf16.bf16.f32 "
        "{%0,%1,%2,%3}, {%4,%5,%6,%7}, {%8,%9}, {%0,%1,%2,%3};"
        : "+f"(c[0]), "+f"(c[1]), "+f"(c[2]), "+f"(c[3])
        : "r"(a[0]), "r"(a[1]), "r"(a[2]), "r"(a[3]), "r"(b0), "r"(b1));
}

// ---------------- weight transpose + split:  w[K,N] -> wt_hi/lo[N,K] -------
__global__ __launch_bounds__(256) void wsplit_kernel(
    const float* __restrict__ w, __nv_bfloat16* __restrict__ whi,
    __nv_bfloat16* __restrict__ wlo, int K, int N)
{
    __shared__ float t[32][33];
    int n0 = blockIdx.x * 32, k0 = blockIdx.y * 32;
    int tx = threadIdx.x & 31, ty = threadIdx.x >> 5;
    #pragma unroll
    for (int j = 0; j < 4; j++)
        t[ty + j * 8][tx] = w[(size_t)(k0 + ty + j * 8) * N + n0 + tx];
    __syncthreads();
    #pragma unroll
    for (int j = 0; j < 4; j++) {
        int nn = ty + j * 8;
        float v = t[tx][nn];
        __nv_bfloat16 h, l; bf_split(v, h, l);
        size_t o = (size_t)(n0 + nn) * K + k0 + tx;
        whi[o] = h; wlo[o] = l;
    }
}

// ---------------- LayerNorm -> split bf16 -----------------------------------
__global__ __launch_bounds__(256) void ln_split_kernel(
    const float* __restrict__ x, const float* __restrict__ g,
    const float* __restrict__ b, __nv_bfloat16* __restrict__ oh,
    __nv_bfloat16* __restrict__ ol)
{
    int row = blockIdx.x;
    const float* xr = x + (size_t)row * DD;
    float s = 0.f, s2 = 0.f;
    for (int i = threadIdx.x; i < DD; i += 256) {
        float v = xr[i]; s += v; s2 += v * v;
    }
    __shared__ float red[8], red2[8], stats[2];
    for (int off = 16; off > 0; off >>= 1) {
        s  += __shfl_down_sync(0xffffffffu, s,  off);
        s2 += __shfl_down_sync(0xffffffffu, s2, off);
    }
    int wid = threadIdx.x >> 5, lid = threadIdx.x & 31;
    if (lid == 0) { red[wid] = s; red2[wid] = s2; }
    __syncthreads();
    if (threadIdx.x == 0) {
        float ts = 0.f, ts2 = 0.f;
        for (int i = 0; i < 8; i++) { ts += red[i]; ts2 += red2[i]; }
        float mu = ts * (1.0f / DD);
        float var = ts2 * (1.0f / DD) - mu * mu;
        stats[0] = mu; stats[1] = rsqrtf(var + 1e-5f);
    }
    __syncthreads();
    float mu = stats[0], rstd = stats[1];
    for (int i = threadIdx.x; i < DD; i += 256) {
        float v = (xr[i] - mu) * rstd * g[i] + b[i];
        __nv_bfloat16 h, l; bf_split(v, h, l);
        oh[(size_t)row * DD + i] = h;
        ol[(size_t)row * DD + i] = l;
    }
}

// ---------------- mma.sync split-bf16 GEMM (3-stage pipeline) ---------------
#define SPAD 72
#define TEN_BYTES (128 * SPAD * 2)
#define STAGE_BYTES (4 * TEN_BYTES)
#define GSTAGES 3
#define GEMM_SMEM (GSTAGES * STAGE_BYTES)   // 221184

template <int MODE>
__global__ __launch_bounds__(256, 1) void gemm_mma(
    const __nv_bfloat16* __restrict__ Ahi, const __nv_bfloat16* __restrict__ Alo,
    const __nv_bfloat16* __restrict__ Bhi, const __nv_bfloat16* __restrict__ Blo,
    float* __restrict__ Cf, const float* __restrict__ aux,
    __nv_bfloat16* __restrict__ Chi, __nv_bfloat16* __restrict__ Clo,
    int M, int N, int K)
{
    extern __shared__ char smem[];
    const uint32_t sbase = smem_u32(smem);
    const int tid = threadIdx.x, lane = tid & 31, wid = tid >> 5;
    const int wm = wid & 1, wn = wid >> 1;
    const int bx = blockIdx.x, by = blockIdx.y;

    const size_t rowbytes = (size_t)K * 2;
    const char* base[4] = {
        (const char*)(Ahi + (size_t)by * 128 * K),
        (const char*)(Alo + (size_t)by * 128 * K),
        (const char*)(Bhi + (size_t)bx * 128 * K),
        (const char*)(Blo + (size_t)bx * 128 * K)
    };

    const uint32_t aRowOff = (uint32_t)((wm * 64 + (lane & 15)) * (SPAD * 2) + (lane >> 4) * 16);
    const int bg = lane >> 3;
    const uint32_t bRowOff = (uint32_t)((wn * 32 + (bg >> 1) * 8 + (lane & 7)) * (SPAD * 2) + (bg & 1) * 16);

    auto load_slab = [&](int ks, int st) {
        uint32_t stg = sbase + (uint32_t)st * STAGE_BYTES;
        size_t koff = (size_t)ks * 128;
        #pragma unroll
        for (int i = 0; i < 16; i++) {
            int c = tid + i * 256;
            int tn = c >> 10;
            int rr = (c >> 3) & 127;
            int ck = (c & 7) * 16;
            cp16(stg + (uint32_t)(tn * TEN_BYTES + rr * (SPAD * 2) + ck),
                 base[tn] + (size_t)rr * rowbytes + koff + ck);
        }
        asm volatile("cp.async.commit_group;" ::: "memory");
    };

    float acc[4][4][4];
    #pragma unroll
    for (int mt = 0; mt < 4; mt++)
        #pragma unroll
        for (int nt = 0; nt < 4; nt++)
            #pragma unroll
            for (int j = 0; j < 4; j++) acc[mt][nt][j] = 0.f;

    const int ns = K >> 6;
    load_slab(0, 0);
    if (ns > 1) load_slab(1, 1);

    for (int i = 0; i < ns; i++) {
        if (i + 1 < ns) asm volatile("cp.async.wait_group 1;" ::: "memory");
        else            asm volatile("cp.async.wait_group 0;" ::: "memory");
        __syncthreads();
        if (i + 2 < ns) load_slab(i + 2, (i + 2) % GSTAGES);

        uint32_t stg = sbase + (uint32_t)(i % GSTAGES) * STAGE_BYTES;
        uint32_t aHiB = stg + aRowOff;
        uint32_t aLoB = stg + TEN_BYTES + aRowOff;
        uint32_t bHiB = stg + 2 * TEN_BYTES + bRowOff;
        uint32_t bLoB = stg + 3 * TEN_BYTES + bRowOff;

        #pragma unroll
        for (int ks = 0; ks < 4; ks++) {
            uint32_t ah[4][4], al[4][4], bh[2][4], bl[2][4];
            #pragma unroll
            for (int mt = 0; mt < 4; mt++) {
                uint32_t o = (uint32_t)(mt * 16 * (SPAD * 2) + ks * 32);
                ldsm4(ah[mt], aHiB + o);
                ldsm4(al[mt], aLoB + o);
            }
            #pragma unroll
            for (int p = 0; p < 2; p++) {
                uint32_t o = (uint32_t)(p * 16 * (SPAD * 2) + ks * 32);
                ldsm4(bh[p], bHiB + o);
                ldsm4(bl[p], bLoB + o);
            }
            #pragma unroll
            for (int mt = 0; mt < 4; mt++) {
                #pragma unroll
                for (int nt = 0; nt < 4; nt++) {
                    int p = nt >> 1, o = (nt & 1) * 2;
                    mma16816(acc[mt][nt], ah[mt], bh[p][o], bh[p][o + 1]);
                    mma16816(acc[mt][nt], ah[mt], bl[p][o], bl[p][o + 1]);
                    mma16816(acc[mt][nt], al[mt], bh[p][o], bh[p][o + 1]);
                }
            }
        }
    }

    // ----- epilogue ----------------------------------------------------------
    const int groupID = lane >> 2, tid4 = lane & 3;
    #pragma unroll
    for (int mt = 0; mt < 4; mt++) {
        int r0 = by * 128 + wm * 64 + mt * 16 + groupID;
        #pragma unroll
        for (int nt = 0; nt < 4; nt++) {
            int cg = bx * 128 + wn * 32 + nt * 8 + tid4 * 2;
            float* a = acc[mt][nt];
            #pragma unroll
            for (int half = 0; half < 2; half++) {
                size_t off = (size_t)(r0 + half * 8) * N + cg;
                float v0 = a[half * 2 + 0], v1 = a[half * 2 + 1];
                if (MODE == 0) {
                    float2 o; o.x = silu(v0); o.y = silu(v1);
                    *(float2*)(Cf + off) = o;
                } else if (MODE == 1) {
                    float2 ax = *(const float2*)(aux + off);
                    float2 o; o.x = v0 + ax.x; o.y = v1 + ax.y;
                    *(float2*)(Cf + off) = o;
                } else {
                    float2 ax = *(const float2*)(aux + off);
                    float t0 = v0 * ax.x, t1 = v1 * ax.y;
                    __nv_bfloat16 h0, l0, h1, l1;
                    bf_split(t0, h0, l0);
                    bf_split(t1, h1, l1);
                    *(uint32_t*)(Chi + off) = pack2(h0, h1);
                    *(uint32_t*)(Clo + off) = pack2(l0, l1);
                }
            }
        }
    }
}

// ---------------- Fused attention with mma.sync -----------------------------
// Per block: 128 q rows of one (b,h). Iter over 128-key tiles (causal).
// QK^T (3-term split) -> silu/mask -> S split -> S@V (3-term) -> headLN*u.
// smem layout (bytes from base):
//  Qhi 0, Qlo 18432, Khi 36864, Klo 55296,
//  Vthi 73728 (64x136 bf16 = 17408), Vtlo 91136,
//  Shi 108544 (128x136 bf16 = 34816), Slo 143360.  total 178176
//  'a' fp32 [128][68] aliases Shi region after the loop.
#define ATT_SMEM 178176
#define QSTRB 144      // Q/K row stride bytes (72 bf16)
#define VSTRB 272      // Vt/S row stride bytes (136 bf16)

__global__ __launch_bounds__(256, 1) void attn_mma(
    const float* __restrict__ qkuv, const float* __restrict__ nag,
    const float* __restrict__ nab, __nv_bfloat16* __restrict__ ahi,
    __nv_bfloat16* __restrict__ alo)
{
    extern __shared__ char smc[];
    const uint32_t sb = smem_u32(smc);
    const uint32_t oQh = 0, oQl = 18432, oKh = 36864, oKl = 55296;
    const uint32_t oVh = 73728, oVl = 91136, oSh = 108544, oSl = 143360;
    __nv_bfloat16* qhp = (__nv_bfloat16*)(smc + oQh);
    __nv_bfloat16* qlp = (__nv_bfloat16*)(smc + oQl);
    __nv_bfloat16* khp = (__nv_bfloat16*)(smc + oKh);
    __nv_bfloat16* klp = (__nv_bfloat16*)(smc + oKl);
    __nv_bfloat16* vhp = (__nv_bfloat16*)(smc + oVh);
    __nv_bfloat16* vlp = (__nv_bfloat16*)(smc + oVl);
    __nv_bfloat16* shp = (__nv_bfloat16*)(smc + oSh);
    __nv_bfloat16* slp = (__nv_bfloat16*)(smc + oSl);
    float* aS = (float*)(smc + oSh);      // [128][68] fp32, aliases S after loop
    __shared__ float mu_s[128], rs_s[128];

    const int qb = blockIdx.x, bh = blockIdx.y;
    const int b = bh >> 4, h = bh & 15;
    const int tid = threadIdx.x, lane = tid & 31, wid = tid >> 5;
    const int wm = wid & 1, wn = wid >> 1;
    const int groupID = lane >> 2, tid4 = lane & 3;
    const size_t rs = 4 * DD;
    const float* base = qkuv + (size_t)(b * LL) * rs + h * HD;

    // ---- load Q (128x64 fp32) -> split bf16 ----
    {
        const float* Qg = base + (size_t)(qb * 128) * rs;
        #pragma unroll
        for (int i = 0; i < 8; i++) {
            int idx = tid + i * 256;
            int r = idx >> 4, c4 = (idx & 15) * 4;
            float4 v = *(const float4*)(Qg + (size_t)r * rs + c4);
            __nv_bfloat16 h0,l0,h1,l1,h2,l2,h3,l3;
            bf_split(v.x,h0,l0); bf_split(v.y,h1,l1); bf_split(v.z,h2,l2); bf_split(v.w,h3,l3);
            *(uint2*)(qhp + r * 72 + c4) = make_uint2(pack2(h0,h1), pack2(h2,h3));
            *(uint2*)(qlp + r * 72 + c4) = make_uint2(pack2(l0,l1), pack2(l2,l3));
        }
    }

    const uint32_t aOffQ = (uint32_t)((wm * 64 + (lane & 15)) * QSTRB + (lane >> 4) * 16);
    const int bg = lane >> 3;
    const uint32_t bOffK = (uint32_t)((wn * 32 + (bg >> 1) * 8 + (lane & 7)) * QSTRB + (bg & 1) * 16);
    const uint32_t aOffS = (uint32_t)((wm * 64 + (lane & 15)) * VSTRB + (lane >> 4) * 16);
    const uint32_t bOffV = (uint32_t)((wn * 16 + (bg >> 1) * 8 + (lane & 7)) * VSTRB + (bg & 1) * 16);

    float oacc[4][2][4];
    #pragma unroll
    for (int mt = 0; mt < 4; mt++)
        #pragma unroll
        for (int nt = 0; nt < 2; nt++)
            #pragma unroll
            for (int j = 0; j < 4; j++) oacc[mt][nt][j] = 0.f;

    for (int kb = 0; kb <= qb; kb++) {
        __syncthreads();   // smem free (prev SV done); Q visible on first iter
        // ---- load K tile -> split; V tile -> transposed split ----
        {
            const float* Kg = base + DD + (size_t)(kb * 128) * rs;
            const float* Vg = base + 2 * DD + (size_t)(kb * 128) * rs;
            #pragma unroll
            for (int i = 0; i < 8; i++) {
                int idx = tid + i * 256;
                int r = idx >> 4, c4 = (idx & 15) * 4;
                float4 v = *(const float4*)(Kg + (size_t)r * rs + c4);
                __nv_bfloat16 h0,l0,h1,l1,h2,l2,h3,l3;
                bf_split(v.x,h0,l0); bf_split(v.y,h1,l1); bf_split(v.z,h2,l2); bf_split(v.w,h3,l3);
                *(uint2*)(khp + r * 72 + c4) = make_uint2(pack2(h0,h1), pack2(h2,h3));
                *(uint2*)(klp + r * 72 + c4) = make_uint2(pack2(l0,l1), pack2(l2,l3));
                float4 vv = *(const float4*)(Vg + (size_t)r * rs + c4);
                __nv_bfloat16 vh0,vl0,vh1,vl1,vh2,vl2,vh3,vl3;
                bf_split(vv.x,vh0,vl0); bf_split(vv.y,vh1,vl1);
                bf_split(vv.z,vh2,vl2); bf_split(vv.w,vh3,vl3);
                vhp[(c4+0)*136 + r] = vh0; vhp[(c4+1)*136 + r] = vh1;
                vhp[(c4+2)*136 + r] = vh2; vhp[(c4+3)*136 + r] = vh3;
                vlp[(c4+0)*136 + r] = vl0; vlp[(c4+1)*136 + r] = vl1;
                vlp[(c4+2)*136 + r] = vl2; vlp[(c4+3)*136 + r] = vl3;
            }
        }
        __syncthreads();

        // ---- S = Q @ K^T (3-term) ----
        float sacc[4][4][4];
        #pragma unroll
        for (int mt = 0; mt < 4; mt++)
            #pragma unroll
            for (int nt = 0; nt < 4; nt++)
                #pragma unroll
                for (int j = 0; j < 4; j++) sacc[mt][nt][j] = 0.f;

        #pragma unroll
        for (int ks = 0; ks < 4; ks++) {
            uint32_t qh[4][4], ql[4][4], kh[2][4], kl[2][4];
            #pragma unroll
            for (int mt = 0; mt < 4; mt++) {
                uint32_t o = (uint32_t)(mt * 16 * QSTRB + ks * 32);
                ldsm4(qh[mt], sb + oQh + aOffQ + o);
                ldsm4(ql[mt], sb + oQl + aOffQ + o);
            }
            #pragma unroll
            for (int p = 0; p < 2; p++) {
                uint32_t o = (uint32_t)(p * 16 * QSTRB + ks * 32);
                ldsm4(kh[p], sb + oKh + bOffK + o);
                ldsm4(kl[p], sb + oKl + bOffK + o);
            }
            #pragma unroll
            for (int mt = 0; mt < 4; mt++) {
                #pragma unroll
                for (int nt = 0; nt < 4; nt++) {
                    int p = nt >> 1, o = (nt & 1) * 2;
                    mma16816(sacc[mt][nt], qh[mt], kh[p][o], kh[p][o + 1]);
                    mma16816(sacc[mt][nt], qh[mt], kl[p][o], kl[p][o + 1]);
                    mma16816(sacc[mt][nt], ql[mt], kh[p][o], kh[p][o + 1]);
                }
            }
        }

        // ---- silu/scale/mask -> S split to smem ----
        const bool diag = (kb == qb);
        #pragma unroll
        for (int mt = 0; mt < 4; mt++) {
            #pragma unroll
            for (int half = 0; half < 2; half++) {
                int r = wm * 64 + mt * 16 + groupID + half * 8;
                #pragma unroll
                for (int nt = 0; nt < 4; nt++) {
                    int c = wn * 32 + nt * 8 + tid4 * 2;
                    float s0 = silu(sacc[mt][nt][half * 2 + 0] * 0.125f);
                    float s1 = silu(sacc[mt][nt][half * 2 + 1] * 0.125f);
                    if (diag) {
                        if (c > r) s0 = 0.f;
                        if (c + 1 > r) s1 = 0.f;
                    }
                    __nv_bfloat16 h0,l0,h1,l1;
                    bf_split(s0,h0,l0); bf_split(s1,h1,l1);
                    *(uint32_t*)(shp + r * 136 + c) = pack2(h0,h1);
                    *(uint32_t*)(slp + r * 136 + c) = pack2(l0,l1);
                }
            }
        }
        __syncthreads();

        // ---- A += S @ V (3-term), n=64 ----
        #pragma unroll
        for (int ks = 0; ks < 8; ks++) {
            uint32_t sh4[4][4], sl4[4][4], vh4[4], vl4[4];
            #pragma unroll
            for (int mt = 0; mt < 4; mt++) {
                uint32_t o = (uint32_t)(mt * 16 * VSTRB + ks * 32);
                ldsm4(sh4[mt], sb + oSh + aOffS + o);
                ldsm4(sl4[mt], sb + oSl + aOffS + o);
            }
            ldsm4(vh4, sb + oVh + bOffV + (uint32_t)(ks * 32));
            ldsm4(vl4, sb + oVl + bOffV + (uint32_t)(ks * 32));
            #pragma unroll
            for (int mt = 0; mt < 4; mt++) {
                #pragma unroll
                for (int nt = 0; nt < 2; nt++) {
                    int o = nt * 2;
                    mma16816(oacc[mt][nt], sh4[mt], vh4[o], vh4[o + 1]);
                    mma16816(oacc[mt][nt], sh4[mt], vl4[o], vl4[o + 1]);
                    mma16816(oacc[mt][nt], sl4[mt], vh4[o], vh4[o + 1]);
                }
            }
        }
    }

    // ---- write a to smem (fp32, stride 68), LN over d=64, *u, split out ----
    __syncthreads();
    #pragma unroll
    for (int mt = 0; mt < 4; mt++) {
        #pragma unroll
        for (int half = 0; half < 2; half++) {
            int r = wm * 64 + mt * 16 + groupID + half * 8;
            #pragma unroll
            for (int nt = 0; nt < 2; nt++) {
                int c = wn * 16 + nt * 8 + tid4 * 2;
                float2 v;
                v.x = oacc[mt][nt][half * 2 + 0];
                v.y = oacc[mt][nt][half * 2 + 1];
                *(float2*)(aS + r * 68 + c) = v;
            }
        }
    }
    __syncthreads();
    if (tid < 128) {
        float s = 0.f, s2 = 0.f;
        #pragma unroll
        for (int c = 0; c < 64; c++) {
            float v = aS[tid * 68 + c];
            s += v; s2 += v * v;
        }
        float mu = s * (1.0f / 64.0f);
        float var = s2 * (1.0f / 64.0f) - mu * mu;
        mu_s[tid] = mu;
        rs_s[tid] = rsqrtf(var + 1e-5f);
    }
    __syncthreads();
    {
        int r = tid >> 1;
        int c0 = (tid & 1) * 32;
        int l = qb * 128 + r;
        float mu = mu_s[r], rstd = rs_s[r];
        const float* urow = base + 3 * DD + (size_t)l * rs;
        size_t obase = (size_t)(b * LL + l) * DD + h * HD;
        #pragma unroll
        for (int c = c0; c < c0 + 32; c += 4) {
            float4 uv = *(const float4*)(urow + c);
            float t0 = ((aS[r * 68 + c + 0] - mu) * rstd * nag[c + 0] + nab[c + 0]) * uv.x;
            float t1 = ((aS[r * 68 + c + 1] - mu) * rstd * nag[c + 1] + nab[c + 1]) * uv.y;
            float t2 = ((aS[r * 68 + c + 2] - mu) * rstd * nag[c + 2] + nab[c + 2]) * uv.z;
            float t3 = ((aS[r * 68 + c + 3] - mu) * rstd * nag[c + 3] + nab[c + 3]) * uv.w;
            __nv_bfloat16 h0,l0,h1,l1,h2,l2,h3,l3;
            bf_split(t0,h0,l0); bf_split(t1,h1,l1); bf_split(t2,h2,l2); bf_split(t3,h3,l3);
            *(uint2*)(ahi + obase + c) = make_uint2(pack2(h0,h1), pack2(h2,h3));
            *(uint2*)(alo + obase + c) = make_uint2(pack2(l0,l1), pack2(l2,l3));
        }
    }
}

// ---------------- host -------------------------------------------------------
extern "C" void kernel_launch(void* const* d_in, const int* in_sizes, int n_in,
                              void* d_out, int out_size)
{
    const float* x      = (const float*)d_in[0];
    const float* w_qkuv = (const float*)d_in[2];
    const float* w_out  = (const float*)d_in[3];
    const float* w1     = (const float*)d_in[4];
    const float* w2     = (const float*)d_in[5];
    const float* w3     = (const float*)d_in[6];
    const float* ln1_g  = (const float*)d_in[7];
    const float* ln1_b  = (const float*)d_in[8];
    const float* ln2_g  = (const float*)d_in[9];
    const float* ln2_b  = (const float*)d_in[10];
    const float* na_g   = (const float*)d_in[11];
    const float* na_b   = (const float*)d_in[12];
    float* out = (float*)d_out;

    __nv_bfloat16 *xnh, *xnl, *ah, *al, *xn2h, *xn2l, *hh, *hl;
    __nv_bfloat16 *wqh, *wql, *woh, *wol, *w1h, *w1l, *w3h, *w3l, *w2h, *w2l;
    float *qkuv, *x1, *h1;
    cudaGetSymbolAddress((void**)&xnh,  g_xn_hi);  cudaGetSymbolAddress((void**)&xnl,  g_xn_lo);
    cudaGetSymbolAddress((void**)&qkuv, g_qkuv);
    cudaGetSymbolAddress((void**)&ah,   g_a_hi);   cudaGetSymbolAddress((void**)&al,   g_a_lo);
    cudaGetSymbolAddress((void**)&x1,   g_x1);
    cudaGetSymbolAddress((void**)&xn2h, g_xn2_hi); cudaGetSymbolAddress((void**)&xn2l, g_xn2_lo);
    cudaGetSymbolAddress((void**)&h1,   g_h1);
    cudaGetSymbolAddress((void**)&hh,   g_h_hi);   cudaGetSymbolAddress((void**)&hl,   g_h_lo);
    cudaGetSymbolAddress((void**)&wqh,  g_wqkuv_hi); cudaGetSymbolAddress((void**)&wql, g_wqkuv_lo);
    cudaGetSymbolAddress((void**)&woh,  g_wout_hi);  cudaGetSymbolAddress((void**)&wol, g_wout_lo);
    cudaGetSymbolAddress((void**)&w1h,  g_w1_hi);    cudaGetSymbolAddress((void**)&w1l, g_w1_lo);
    cudaGetSymbolAddress((void**)&w3h,  g_w3_hi);    cudaGetSymbolAddress((void**)&w3l, g_w3_lo);
    cudaGetSymbolAddress((void**)&w2h,  g_w2_hi);    cudaGetSymbolAddress((void**)&w2l, g_w2_lo);

    cudaFuncSetAttribute(gemm_mma<0>, cudaFuncAttributeMaxDynamicSharedMemorySize, GEMM_SMEM);
    cudaFuncSetAttribute(gemm_mma<1>, cudaFuncAttributeMaxDynamicSharedMemorySize, GEMM_SMEM);
    cudaFuncSetAttribute(gemm_mma<2>, cudaFuncAttributeMaxDynamicSharedMemorySize, GEMM_SMEM);
    cudaFuncSetAttribute(attn_mma,    cudaFuncAttributeMaxDynamicSharedMemorySize, ATT_SMEM);

    dim3 blk(256);

    // 0. weight transpose + split
    wsplit_kernel<<<dim3(4 * DD / 32, DD / 32), blk>>>(w_qkuv, wqh, wql, DD, 4 * DD);
    wsplit_kernel<<<dim3(DD / 32, DD / 32),     blk>>>(w_out,  woh, wol, DD, DD);
    wsplit_kernel<<<dim3(FF / 32, DD / 32),     blk>>>(w1,     w1h, w1l, DD, FF);
    wsplit_kernel<<<dim3(FF / 32, DD / 32),     blk>>>(w3,     w3h, w3l, DD, FF);
    wsplit_kernel<<<dim3(DD / 32, FF / 32),     blk>>>(w2,     w2h, w2l, FF, DD);

    // 1. LN1 -> split
    ln_split_kernel<<<MROWS, blk>>>(x, ln1_g, ln1_b, xnh, xnl);
    // 2. qkuv = silu(xn @ w_qkuv)
    gemm_mma<0><<<dim3(4 * DD / 128, MROWS / 128), blk, GEMM_SMEM>>>(
        xnh, xnl, wqh, wql, qkuv, nullptr, nullptr, nullptr, MROWS, 4 * DD, DD);
    // 3. attention -> a hi/lo
    attn_mma<<<dim3(LL / 128, BB * HH), blk, ATT_SMEM>>>(qkuv, na_g, na_b, ah, al);
    // 4. x1 = x + a @ w_out
    gemm_mma<1><<<dim3(DD / 128, MROWS / 128), blk, GEMM_SMEM>>>(
        ah, al, woh, wol, x1, x, nullptr, nullptr, MROWS, DD, DD);
    // 5. LN2 -> split
    ln_split_kernel<<<MROWS, blk>>>(x1, ln2_g, ln2_b, xn2h, xn2l);
    // 6. h1 = silu(xn2 @ w1)
    gemm_mma<0><<<dim3(FF / 128, MROWS / 128), blk, GEMM_SMEM>>>(
        xn2h, xn2l, w1h, w1l, h1, nullptr, nullptr, nullptr, MROWS, FF, DD);
    // 7. h = (xn2 @ w3) * h1 -> hi/lo
    gemm_mma<2><<<dim3(FF / 128, MROWS / 128), blk, GEMM_SMEM>>>(
        xn2h, xn2l, w3h, w3l, nullptr, h1, hh, hl, MROWS, FF, DD);
    // 8. out = x1 + h @ w2
    gemm_mma<1><<<dim3(DD / 128, MROWS / 128), blk, GEMM_SMEM>>>(
        hh, hl, w2h, w2l, out, x1, nullptr, nullptr, MROWS, DD, FF);
}

// round 5
// speedup vs baseline: 2.6779x; 1.0748x over previous
#include <cuda_runtime.h>
#include <cuda_bf16.h>
#include <cstdint>
#include <math.h>

#define BB 2
#define LL 2048
#define DD 1024
#define HH 16
#define HD 64
#define FF 4096
#define MROWS (BB*LL)   // 4096

// ---------------- scratch (device globals) ---------------------------------
__device__ __nv_bfloat16 g_xn_hi [MROWS * DD];
__device__ __nv_bfloat16 g_xn_lo [MROWS * DD];
__device__ __nv_bfloat16 g_qk_hi [MROWS * 4 * DD];   // silu(xn@w_qkuv) split
__device__ __nv_bfloat16 g_qk_lo [MROWS * 4 * DD];
__device__ __nv_bfloat16 g_a_hi  [MROWS * DD];
__device__ __nv_bfloat16 g_a_lo  [MROWS * DD];
__device__ float         g_x1    [MROWS * DD];
__device__ __nv_bfloat16 g_xn2_hi[MROWS * DD];
__device__ __nv_bfloat16 g_xn2_lo[MROWS * DD];
__device__ __nv_bfloat16 g_h_hi  [MROWS * FF];
__device__ __nv_bfloat16 g_h_lo  [MROWS * FF];
// transposed + split weights: [N, K] K-major
__device__ __nv_bfloat16 g_wqkuv_hi[4 * DD * DD];
__device__ __nv_bfloat16 g_wqkuv_lo[4 * DD * DD];
__device__ __nv_bfloat16 g_wout_hi [DD * DD];
__device__ __nv_bfloat16 g_wout_lo [DD * DD];
__device__ __nv_bfloat16 g_w1_hi   [DD * FF];
__device__ __nv_bfloat16 g_w1_lo   [DD * FF];
__device__ __nv_bfloat16 g_w3_hi   [DD * FF];
__device__ __nv_bfloat16 g_w3_lo   [DD * FF];
__device__ __nv_bfloat16 g_w2_hi   [FF * DD];
__device__ __nv_bfloat16 g_w2_lo   [FF * DD];

__device__ __forceinline__ float silu(float x) {
    return __fdividef(x, 1.0f + __expf(-x));
}
__device__ __forceinline__ uint32_t smem_u32(const void* p) {
    uint32_t a;
    asm("{ .reg .u64 t; cvta.to.shared.u64 t, %1; cvt.u32.u64 %0, t; }" : "=r"(a) : "l"(p));
    return a;
}
__device__ __forceinline__ void cp16(uint32_t s, const void* g) {
    asm volatile("cp.async.cg.shared.global [%0], [%1], 16;" :: "r"(s), "l"(g) : "memory");
}
__device__ __forceinline__ void bf_split(float v, __nv_bfloat16& h, __nv_bfloat16& l) {
    h = __float2bfloat16(v);
    l = __float2bfloat16(v - __bfloat162float(h));
}
__device__ __forceinline__ uint32_t pack2(__nv_bfloat16 a, __nv_bfloat16 b) {
    return (uint32_t)__bfloat16_as_ushort(a) | ((uint32_t)__bfloat16_as_ushort(b) << 16);
}
__device__ __forceinline__ void ldsm4(uint32_t* r, uint32_t a) {
    asm volatile("ldmatrix.sync.aligned.m8n8.x4.shared.b16 {%0,%1,%2,%3}, [%4];"
        : "=r"(r[0]), "=r"(r[1]), "=r"(r[2]), "=r"(r[3]) : "r"(a));
}
__device__ __forceinline__ void ldsm4t(uint32_t* r, uint32_t a) {
    asm volatile("ldmatrix.sync.aligned.m8n8.x4.trans.shared.b16 {%0,%1,%2,%3}, [%4];"
        : "=r"(r[0]), "=r"(r[1]), "=r"(r[2]), "=r"(r[3]) : "r"(a));
}
__device__ __forceinline__ void mma16816(float* c, const uint32_t* a, uint32_t b0, uint32_t b1) {
    asm volatile(
        "mma.sync.aligned.m16n8k16.row.col.f32.bf16.bf16.f32 "
        "{%0,%1,%2,%3}, {%4,%5,%6,%7}, {%8,%9}, {%0,%1,%2,%3};"
        : "+f"(c[0]), "+f"(c[1]), "+f"(c[2]), "+f"(c[3])
        : "r"(a[0]), "r"(a[1]), "r"(a[2]), "r"(a[3]), "r"(b0), "r"(b1));
}

// ---------------- weight transpose + split ----------------------------------
__global__ __launch_bounds__(256) void wsplit_kernel(
    const float* __restrict__ w, __nv_bfloat16* __restrict__ whi,
    __nv_bfloat16* __restrict__ wlo, int K, int N)
{
    __shared__ float t[32][33];
    int n0 = blockIdx.x * 32, k0 = blockIdx.y * 32;
    int tx = threadIdx.x & 31, ty = threadIdx.x >> 5;
    #pragma unroll
    for (int j = 0; j < 4; j++)
        t[ty + j * 8][tx] = w[(size_t)(k0 + ty + j * 8) * N + n0 + tx];
    __syncthreads();
    #pragma unroll
    for (int j = 0; j < 4; j++) {
        int nn = ty + j * 8;
        float v = t[tx][nn];
        __nv_bfloat16 h, l; bf_split(v, h, l);
        size_t o = (size_t)(n0 + nn) * K + k0 + tx;
        whi[o] = h; wlo[o] = l;
    }
}

// ---------------- LayerNorm -> split bf16 -----------------------------------
__global__ __launch_bounds__(256) void ln_split_kernel(
    const float* __restrict__ x, const float* __restrict__ g,
    const float* __restrict__ b, __nv_bfloat16* __restrict__ oh,
    __nv_bfloat16* __restrict__ ol)
{
    int row = blockIdx.x;
    const float* xr = x + (size_t)row * DD;
    float s = 0.f, s2 = 0.f;
    for (int i = threadIdx.x; i < DD; i += 256) {
        float v = xr[i]; s += v; s2 += v * v;
    }
    __shared__ float red[8], red2[8], stats[2];
    for (int off = 16; off > 0; off >>= 1) {
        s  += __shfl_down_sync(0xffffffffu, s,  off);
        s2 += __shfl_down_sync(0xffffffffu, s2, off);
    }
    int wid = threadIdx.x >> 5, lid = threadIdx.x & 31;
    if (lid == 0) { red[wid] = s; red2[wid] = s2; }
    __syncthreads();
    if (threadIdx.x == 0) {
        float ts = 0.f, ts2 = 0.f;
        for (int i = 0; i < 8; i++) { ts += red[i]; ts2 += red2[i]; }
        float mu = ts * (1.0f / DD);
        float var = ts2 * (1.0f / DD) - mu * mu;
        stats[0] = mu; stats[1] = rsqrtf(var + 1e-5f);
    }
    __syncthreads();
    float mu = stats[0], rstd = stats[1];
    for (int i = threadIdx.x; i < DD; i += 256) {
        float v = (xr[i] - mu) * rstd * g[i] + b[i];
        __nv_bfloat16 h, l; bf_split(v, h, l);
        oh[(size_t)row * DD + i] = h;
        ol[(size_t)row * DD + i] = l;
    }
}

// ---------------- mma.sync split-bf16 GEMM (3-stage) -------------------------
// MODE 1: Cf = acc + aux (fp32 out).  MODE 3: silu(acc) -> Chi/Clo split.
#define SPAD 72
#define TEN_BYTES (128 * SPAD * 2)
#define STAGE_BYTES (4 * TEN_BYTES)
#define GSTAGES 3
#define GEMM_SMEM (GSTAGES * STAGE_BYTES)   // 221184

template <int MODE>
__global__ __launch_bounds__(256, 1) void gemm_mma(
    const __nv_bfloat16* __restrict__ Ahi, const __nv_bfloat16* __restrict__ Alo,
    const __nv_bfloat16* __restrict__ Bhi, const __nv_bfloat16* __restrict__ Blo,
    float* __restrict__ Cf, const float* __restrict__ aux,
    __nv_bfloat16* __restrict__ Chi, __nv_bfloat16* __restrict__ Clo,
    int M, int N, int K)
{
    extern __shared__ char smem[];
    const uint32_t sbase = smem_u32(smem);
    const int tid = threadIdx.x, lane = tid & 31, wid = tid >> 5;
    const int wm = wid & 1, wn = wid >> 1;
    const int bx = blockIdx.x, by = blockIdx.y;

    const size_t rowbytes = (size_t)K * 2;
    const char* base[4] = {
        (const char*)(Ahi + (size_t)by * 128 * K),
        (const char*)(Alo + (size_t)by * 128 * K),
        (const char*)(Bhi + (size_t)bx * 128 * K),
        (const char*)(Blo + (size_t)bx * 128 * K)
    };

    const uint32_t aRowOff = (uint32_t)((wm * 64 + (lane & 15)) * (SPAD * 2) + (lane >> 4) * 16);
    const int bg = lane >> 3;
    const uint32_t bRowOff = (uint32_t)((wn * 32 + (bg >> 1) * 8 + (lane & 7)) * (SPAD * 2) + (bg & 1) * 16);

    auto load_slab = [&](int ks, int st) {
        uint32_t stg = sbase + (uint32_t)st * STAGE_BYTES;
        size_t koff = (size_t)ks * 128;
        #pragma unroll
        for (int i = 0; i < 16; i++) {
            int c = tid + i * 256;
            int tn = c >> 10;
            int rr = (c >> 3) & 127;
            int ck = (c & 7) * 16;
            cp16(stg + (uint32_t)(tn * TEN_BYTES + rr * (SPAD * 2) + ck),
                 base[tn] + (size_t)rr * rowbytes + koff + ck);
        }
        asm volatile("cp.async.commit_group;" ::: "memory");
    };

    float acc[4][4][4];
    #pragma unroll
    for (int mt = 0; mt < 4; mt++)
        #pragma unroll
        for (int nt = 0; nt < 4; nt++)
            #pragma unroll
            for (int j = 0; j < 4; j++) acc[mt][nt][j] = 0.f;

    const int ns = K >> 6;
    load_slab(0, 0);
    if (ns > 1) load_slab(1, 1);

    for (int i = 0; i < ns; i++) {
        if (i + 1 < ns) asm volatile("cp.async.wait_group 1;" ::: "memory");
        else            asm volatile("cp.async.wait_group 0;" ::: "memory");
        __syncthreads();
        if (i + 2 < ns) load_slab(i + 2, (i + 2) % GSTAGES);

        uint32_t stg = sbase + (uint32_t)(i % GSTAGES) * STAGE_BYTES;
        uint32_t aHiB = stg + aRowOff;
        uint32_t aLoB = stg + TEN_BYTES + aRowOff;
        uint32_t bHiB = stg + 2 * TEN_BYTES + bRowOff;
        uint32_t bLoB = stg + 3 * TEN_BYTES + bRowOff;

        #pragma unroll
        for (int ks = 0; ks < 4; ks++) {
            uint32_t ah[4][4], al[4][4], bh[2][4], bl[2][4];
            #pragma unroll
            for (int mt = 0; mt < 4; mt++) {
                uint32_t o = (uint32_t)(mt * 16 * (SPAD * 2) + ks * 32);
                ldsm4(ah[mt], aHiB + o);
                ldsm4(al[mt], aLoB + o);
            }
            #pragma unroll
            for (int p = 0; p < 2; p++) {
                uint32_t o = (uint32_t)(p * 16 * (SPAD * 2) + ks * 32);
                ldsm4(bh[p], bHiB + o);
                ldsm4(bl[p], bLoB + o);
            }
            #pragma unroll
            for (int mt = 0; mt < 4; mt++) {
                #pragma unroll
                for (int nt = 0; nt < 4; nt++) {
                    int p = nt >> 1, o = (nt & 1) * 2;
                    mma16816(acc[mt][nt], ah[mt], bh[p][o], bh[p][o + 1]);
                    mma16816(acc[mt][nt], ah[mt], bl[p][o], bl[p][o + 1]);
                    mma16816(acc[mt][nt], al[mt], bh[p][o], bh[p][o + 1]);
                }
            }
        }
    }

    const int groupID = lane >> 2, tid4 = lane & 3;
    #pragma unroll
    for (int mt = 0; mt < 4; mt++) {
        int r0 = by * 128 + wm * 64 + mt * 16 + groupID;
        #pragma unroll
        for (int nt = 0; nt < 4; nt++) {
            int cg = bx * 128 + wn * 32 + nt * 8 + tid4 * 2;
            float* a = acc[mt][nt];
            #pragma unroll
            for (int half = 0; half < 2; half++) {
                size_t off = (size_t)(r0 + half * 8) * N + cg;
                float v0 = a[half * 2 + 0], v1 = a[half * 2 + 1];
                if (MODE == 1) {
                    float2 ax = *(const float2*)(aux + off);
                    float2 o; o.x = v0 + ax.x; o.y = v1 + ax.y;
                    *(float2*)(Cf + off) = o;
                } else {
                    float t0 = silu(v0), t1 = silu(v1);
                    __nv_bfloat16 h0, l0, h1, l1;
                    bf_split(t0, h0, l0);
                    bf_split(t1, h1, l1);
                    *(uint32_t*)(Chi + off) = pack2(h0, h1);
                    *(uint32_t*)(Clo + off) = pack2(l0, l1);
                }
            }
        }
    }
}

// ---------------- dual GEMM: h = silu(A@W1) * (A@W3) -> split ----------------
#define DSTAGE_BYTES (6 * TEN_BYTES)      // 110592
#define DUAL_SMEM (2 * DSTAGE_BYTES)      // 221184

__global__ __launch_bounds__(256, 1) void gemm_dual(
    const __nv_bfloat16* __restrict__ Ahi, const __nv_bfloat16* __restrict__ Alo,
    const __nv_bfloat16* __restrict__ B1hi, const __nv_bfloat16* __restrict__ B1lo,
    const __nv_bfloat16* __restrict__ B3hi, const __nv_bfloat16* __restrict__ B3lo,
    __nv_bfloat16* __restrict__ Chi, __nv_bfloat16* __restrict__ Clo,
    int M, int N, int K)
{
    extern __shared__ char smem[];
    const uint32_t sbase = smem_u32(smem);
    const int tid = threadIdx.x, lane = tid & 31, wid = tid >> 5;
    const int wm = wid & 1, wn = wid >> 1;
    const int bx = blockIdx.x, by = blockIdx.y;

    const size_t rowbytes = (size_t)K * 2;
    const char* base[6] = {
        (const char*)(Ahi  + (size_t)by * 128 * K),
        (const char*)(Alo  + (size_t)by * 128 * K),
        (const char*)(B1hi + (size_t)bx * 128 * K),
        (const char*)(B1lo + (size_t)bx * 128 * K),
        (const char*)(B3hi + (size_t)bx * 128 * K),
        (const char*)(B3lo + (size_t)bx * 128 * K)
    };

    const uint32_t aRowOff = (uint32_t)((wm * 64 + (lane & 15)) * (SPAD * 2) + (lane >> 4) * 16);
    const int bg = lane >> 3;
    const uint32_t bRowOff = (uint32_t)((wn * 32 + (bg >> 1) * 8 + (lane & 7)) * (SPAD * 2) + (bg & 1) * 16);

    auto load_slab = [&](int ks, int st) {
        uint32_t stg = sbase + (uint32_t)st * DSTAGE_BYTES;
        size_t koff = (size_t)ks * 128;
        #pragma unroll
        for (int i = 0; i < 24; i++) {
            int c = tid + i * 256;
            int tn = c >> 10;
            int rr = (c >> 3) & 127;
            int ck = (c & 7) * 16;
            cp16(stg + (uint32_t)(tn * TEN_BYTES + rr * (SPAD * 2) + ck),
                 base[tn] + (size_t)rr * rowbytes + koff + ck);
        }
        asm volatile("cp.async.commit_group;" ::: "memory");
    };

    float acc1[4][4][4], acc3[4][4][4];
    #pragma unroll
    for (int mt = 0; mt < 4; mt++)
        #pragma unroll
        for (int nt = 0; nt < 4; nt++)
            #pragma unroll
            for (int j = 0; j < 4; j++) { acc1[mt][nt][j] = 0.f; acc3[mt][nt][j] = 0.f; }

    const int ns = K >> 6;
    load_slab(0, 0);

    for (int i = 0; i < ns; i++) {
        asm volatile("cp.async.wait_group 0;" ::: "memory");
        __syncthreads();
        if (i + 1 < ns) load_slab(i + 1, (i + 1) & 1);

        uint32_t stg = sbase + (uint32_t)(i & 1) * DSTAGE_BYTES;
        uint32_t aHiB  = stg + aRowOff;
        uint32_t aLoB  = stg + TEN_BYTES + aRowOff;
        uint32_t b1HiB = stg + 2 * TEN_BYTES + bRowOff;
        uint32_t b1LoB = stg + 3 * TEN_BYTES + bRowOff;
        uint32_t b3HiB = stg + 4 * TEN_BYTES + bRowOff;
        uint32_t b3LoB = stg + 5 * TEN_BYTES + bRowOff;

        #pragma unroll
        for (int ks = 0; ks < 4; ks++) {
            uint32_t ah[4][4], al[4][4], bh[2][4], bl[2][4];
            #pragma unroll
            for (int mt = 0; mt < 4; mt++) {
                uint32_t o = (uint32_t)(mt * 16 * (SPAD * 2) + ks * 32);
                ldsm4(ah[mt], aHiB + o);
                ldsm4(al[mt], aLoB + o);
            }
            // ---- W1 ----
            #pragma unroll
            for (int p = 0; p < 2; p++) {
                uint32_t o = (uint32_t)(p * 16 * (SPAD * 2) + ks * 32);
                ldsm4(bh[p], b1HiB + o);
                ldsm4(bl[p], b1LoB + o);
            }
            #pragma unroll
            for (int mt = 0; mt < 4; mt++)
                #pragma unroll
                for (int nt = 0; nt < 4; nt++) {
                    int p = nt >> 1, o = (nt & 1) * 2;
                    mma16816(acc1[mt][nt], ah[mt], bh[p][o], bh[p][o + 1]);
                    mma16816(acc1[mt][nt], ah[mt], bl[p][o], bl[p][o + 1]);
                    mma16816(acc1[mt][nt], al[mt], bh[p][o], bh[p][o + 1]);
                }
            // ---- W3 ----
            #pragma unroll
            for (int p = 0; p < 2; p++) {
                uint32_t o = (uint32_t)(p * 16 * (SPAD * 2) + ks * 32);
                ldsm4(bh[p], b3HiB + o);
                ldsm4(bl[p], b3LoB + o);
            }
            #pragma unroll
            for (int mt = 0; mt < 4; mt++)
                #pragma unroll
                for (int nt = 0; nt < 4; nt++) {
                    int p = nt >> 1, o = (nt & 1) * 2;
                    mma16816(acc3[mt][nt], ah[mt], bh[p][o], bh[p][o + 1]);
                    mma16816(acc3[mt][nt], ah[mt], bl[p][o], bl[p][o + 1]);
                    mma16816(acc3[mt][nt], al[mt], bh[p][o], bh[p][o + 1]);
                }
        }
    }

    const int groupID = lane >> 2, tid4 = lane & 3;
    #pragma unroll
    for (int mt = 0; mt < 4; mt++) {
        int r0 = by * 128 + wm * 64 + mt * 16 + groupID;
        #pragma unroll
        for (int nt = 0; nt < 4; nt++) {
            int cg = bx * 128 + wn * 32 + nt * 8 + tid4 * 2;
            #pragma unroll
            for (int half = 0; half < 2; half++) {
                size_t off = (size_t)(r0 + half * 8) * N + cg;
                float t0 = silu(acc1[mt][nt][half * 2 + 0]) * acc3[mt][nt][half * 2 + 0];
                float t1 = silu(acc1[mt][nt][half * 2 + 1]) * acc3[mt][nt][half * 2 + 1];
                __nv_bfloat16 h0, l0, h1, l1;
                bf_split(t0, h0, l0);
                bf_split(t1, h1, l1);
                *(uint32_t*)(Chi + off) = pack2(h0, h1);
                *(uint32_t*)(Clo + off) = pack2(l0, l1);
            }
        }
    }
}

// ---------------- Fused attention (bf16-split inputs, mma.sync) -------------
// smem: Qh 0, Ql 18432, Kh 36864, Kl 55296, Vh 73728, Vl 92160,
//       Sh 110592 (128x136), Sl 145408.  total 180224. aS aliases Sh.
#define AROWB 144
#define SROWB 272
#define ATT_SMEM 180224
#define GROWB 8192     // global row stride of qkuv split arrays (4096 bf16)

__global__ __launch_bounds__(256, 1) void attn_mma(
    const __nv_bfloat16* __restrict__ qkh, const __nv_bfloat16* __restrict__ qkl,
    const float* __restrict__ nag, const float* __restrict__ nab,
    __nv_bfloat16* __restrict__ ahi, __nv_bfloat16* __restrict__ alo)
{
    extern __shared__ char smc[];
    const uint32_t sb = smem_u32(smc);
    const uint32_t oQh = 0, oQl = 18432, oKh = 36864, oKl = 55296;
    const uint32_t oVh = 73728, oVl = 92160, oSh = 110592, oSl = 145408;
    __nv_bfloat16* shp = (__nv_bfloat16*)(smc + oSh);
    __nv_bfloat16* slp = (__nv_bfloat16*)(smc + oSl);
    float* aS = (float*)(smc + oSh);
    __shared__ float mu_s[128], rs_s[128];

    const int qb = blockIdx.x, bh = blockIdx.y;
    const int b = bh >> 4, h = bh & 15;
    const int tid = threadIdx.x, lane = tid & 31, wid = tid >> 5;
    const int wm = wid & 1, wn = wid >> 1;
    const int groupID = lane >> 2, tid4 = lane & 3;

    const char* gh = (const char*)qkh + (size_t)(b * LL) * GROWB + h * 128;
    const char* gl = (const char*)qkl + (size_t)(b * LL) * GROWB + h * 128;

    auto ldt = [&](uint32_t so, const char* g) {
        #pragma unroll
        for (int i = 0; i < 4; i++) {
            int idx = tid + i * 256;
            int r = idx >> 3, ck = (idx & 7) * 16;
            cp16(sb + so + (uint32_t)(r * AROWB + ck), g + (size_t)r * GROWB + ck);
        }
    };

    // Q tiles (once)
    ldt(oQh, gh + (size_t)(qb * 128) * GROWB);
    ldt(oQl, gl + (size_t)(qb * 128) * GROWB);
    asm volatile("cp.async.commit_group;" ::: "memory");

    const uint32_t aOffQ = (uint32_t)((wm * 64 + (lane & 15)) * AROWB + (lane >> 4) * 16);
    const int bg = lane >> 3;
    const uint32_t bOffK = (uint32_t)((wn * 32 + (bg >> 1) * 8 + (lane & 7)) * AROWB + (bg & 1) * 16);
    const uint32_t aOffS = (uint32_t)((wm * 64 + (lane & 15)) * SROWB + (lane >> 4) * 16);
    // V via ldmatrix.trans on row-major V[k][d]
    const uint32_t bOffV = (uint32_t)(((bg & 1) * 8 + (lane & 7)) * AROWB + (wn * 16 + (bg >> 1) * 8) * 2);

    float oacc[4][2][4];
    #pragma unroll
    for (int mt = 0; mt < 4; mt++)
        #pragma unroll
        for (int nt = 0; nt < 2; nt++)
            #pragma unroll
            for (int j = 0; j < 4; j++) oacc[mt][nt][j] = 0.f;

    for (int kb = 0; kb <= qb; kb++) {
        __syncthreads();   // prev iter done with K/V/S smem
        {
            const char* kh_ = gh + 2048 + (size_t)(kb * 128) * GROWB;
            const char* kl_ = gl + 2048 + (size_t)(kb * 128) * GROWB;
            const char* vh_ = gh + 4096 + (size_t)(kb * 128) * GROWB;
            const char* vl_ = gl + 4096 + (size_t)(kb * 128) * GROWB;
            ldt(oKh, kh_); ldt(oKl, kl_); ldt(oVh, vh_); ldt(oVl, vl_);
        }
        asm volatile("cp.async.commit_group;" ::: "memory");
        asm volatile("cp.async.wait_group 0;" ::: "memory");
        __syncthreads();

        // ---- S = Q @ K^T (3-term) ----
        float sacc[4][4][4];
        #pragma unroll
        for (int mt = 0; mt < 4; mt++)
            #pragma unroll
            for (int nt = 0; nt < 4; nt++)
                #pragma unroll
                for (int j = 0; j < 4; j++) sacc[mt][nt][j] = 0.f;

        #pragma unroll
        for (int ks = 0; ks < 4; ks++) {
            uint32_t qh4[4][4], ql4[4][4], kh4[2][4], kl4[2][4];
            #pragma unroll
            for (int mt = 0; mt < 4; mt++) {
                uint32_t o = (uint32_t)(mt * 16 * AROWB + ks * 32);
                ldsm4(qh4[mt], sb + oQh + aOffQ + o);
                ldsm4(ql4[mt], sb + oQl + aOffQ + o);
            }
            #pragma unroll
            for (int p = 0; p < 2; p++) {
                uint32_t o = (uint32_t)(p * 16 * AROWB + ks * 32);
                ldsm4(kh4[p], sb + oKh + bOffK + o);
                ldsm4(kl4[p], sb + oKl + bOffK + o);
            }
            #pragma unroll
            for (int mt = 0; mt < 4; mt++)
                #pragma unroll
                for (int nt = 0; nt < 4; nt++) {
                    int p = nt >> 1, o = (nt & 1) * 2;
                    mma16816(sacc[mt][nt], qh4[mt], kh4[p][o], kh4[p][o + 1]);
                    mma16816(sacc[mt][nt], qh4[mt], kl4[p][o], kl4[p][o + 1]);
                    mma16816(sacc[mt][nt], ql4[mt], kh4[p][o], kh4[p][o + 1]);
                }
        }

        // ---- silu/scale/mask -> S split to smem ----
        const bool diag = (kb == qb);
        #pragma unroll
        for (int mt = 0; mt < 4; mt++) {
            #pragma unroll
            for (int half = 0; half < 2; half++) {
                int r = wm * 64 + mt * 16 + groupID + half * 8;
                #pragma unroll
                for (int nt = 0; nt < 4; nt++) {
                    int c = wn * 32 + nt * 8 + tid4 * 2;
                    float s0 = silu(sacc[mt][nt][half * 2 + 0] * 0.125f);
                    float s1 = silu(sacc[mt][nt][half * 2 + 1] * 0.125f);
                    if (diag) {
                        if (c > r) s0 = 0.f;
                        if (c + 1 > r) s1 = 0.f;
                    }
                    __nv_bfloat16 h0, l0, h1, l1;
                    bf_split(s0, h0, l0); bf_split(s1, h1, l1);
                    *(uint32_t*)(shp + r * 136 + c) = pack2(h0, h1);
                    *(uint32_t*)(slp + r * 136 + c) = pack2(l0, l1);
                }
            }
        }
        __syncthreads();

        // ---- A += S @ V (3-term, V via ldsm.trans) ----
        #pragma unroll
        for (int ks = 0; ks < 8; ks++) {
            uint32_t sh4[4][4], sl4[4][4], vh4[4], vl4[4];
            #pragma unroll
            for (int mt = 0; mt < 4; mt++) {
                uint32_t o = (uint32_t)(mt * 16 * SROWB + ks * 32);
                ldsm4(sh4[mt], sb + oSh + aOffS + o);
                ldsm4(sl4[mt], sb + oSl + aOffS + o);
            }
            uint32_t vo = (uint32_t)(ks * 16 * AROWB);
            ldsm4t(vh4, sb + oVh + bOffV + vo);
            ldsm4t(vl4, sb + oVl + bOffV + vo);
            #pragma unroll
            for (int mt = 0; mt < 4; mt++)
                #pragma unroll
                for (int nt = 0; nt < 2; nt++) {
                    int o = nt * 2;
                    mma16816(oacc[mt][nt], sh4[mt], vh4[o], vh4[o + 1]);
                    mma16816(oacc[mt][nt], sh4[mt], vl4[o], vl4[o + 1]);
                    mma16816(oacc[mt][nt], sl4[mt], vh4[o], vh4[o + 1]);
                }
        }
    }

    // ---- headLN(d=64) * u, split out ----
    __syncthreads();
    #pragma unroll
    for (int mt = 0; mt < 4; mt++)
        #pragma unroll
        for (int half = 0; half < 2; half++) {
            int r = wm * 64 + mt * 16 + groupID + half * 8;
            #pragma unroll
            for (int nt = 0; nt < 2; nt++) {
                int c = wn * 16 + nt * 8 + tid4 * 2;
                float2 v;
                v.x = oacc[mt][nt][half * 2 + 0];
                v.y = oacc[mt][nt][half * 2 + 1];
                *(float2*)(aS + r * 68 + c) = v;
            }
        }
    __syncthreads();
    if (tid < 128) {
        float s = 0.f, s2 = 0.f;
        #pragma unroll
        for (int c = 0; c < 64; c++) {
            float v = aS[tid * 68 + c];
            s += v; s2 += v * v;
        }
        float mu = s * (1.0f / 64.0f);
        float var = s2 * (1.0f / 64.0f) - mu * mu;
        mu_s[tid] = mu;
        rs_s[tid] = rsqrtf(var + 1e-5f);
    }
    __syncthreads();
    {
        int r = tid >> 1;
        int c0 = (tid & 1) * 32;
        int l = qb * 128 + r;
        float mu = mu_s[r], rstd = rs_s[r];
        const __nv_bfloat16* uh = (const __nv_bfloat16*)(gh + 6144 + (size_t)l * GROWB);
        const __nv_bfloat16* ul = (const __nv_bfloat16*)(gl + 6144 + (size_t)l * GROWB);
        size_t obase = (size_t)(b * LL + l) * DD + h * HD;
        #pragma unroll
        for (int c = c0; c < c0 + 32; c += 2) {
            float u0 = __bfloat162float(uh[c + 0]) + __bfloat162float(ul[c + 0]);
            float u1 = __bfloat162float(uh[c + 1]) + __bfloat162float(ul[c + 1]);
            float t0 = ((aS[r * 68 + c + 0] - mu) * rstd * nag[c + 0] + nab[c + 0]) * u0;
            float t1 = ((aS[r * 68 + c + 1] - mu) * rstd * nag[c + 1] + nab[c + 1]) * u1;
            __nv_bfloat16 h0, l0, h1, l1;
            bf_split(t0, h0, l0); bf_split(t1, h1, l1);
            *(uint32_t*)(ahi + obase + c) = pack2(h0, h1);
            *(uint32_t*)(alo + obase + c) = pack2(l0, l1);
        }
    }
}

// ---------------- host -------------------------------------------------------
extern "C" void kernel_launch(void* const* d_in, const int* in_sizes, int n_in,
                              void* d_out, int out_size)
{
    const float* x      = (const float*)d_in[0];
    const float* w_qkuv = (const float*)d_in[2];
    const float* w_out  = (const float*)d_in[3];
    const float* w1     = (const float*)d_in[4];
    const float* w2     = (const float*)d_in[5];
    const float* w3     = (const float*)d_in[6];
    const float* ln1_g  = (const float*)d_in[7];
    const float* ln1_b  = (const float*)d_in[8];
    const float* ln2_g  = (const float*)d_in[9];
    const float* ln2_b  = (const float*)d_in[10];
    const float* na_g   = (const float*)d_in[11];
    const float* na_b   = (const float*)d_in[12];
    float* out = (float*)d_out;

    __nv_bfloat16 *xnh, *xnl, *qkh, *qkl, *ah, *al, *xn2h, *xn2l, *hh, *hl;
    __nv_bfloat16 *wqh, *wql, *woh, *wol, *w1h, *w1l, *w3h, *w3l, *w2h, *w2l;
    float *x1;
    cudaGetSymbolAddress((void**)&xnh,  g_xn_hi);  cudaGetSymbolAddress((void**)&xnl,  g_xn_lo);
    cudaGetSymbolAddress((void**)&qkh,  g_qk_hi);  cudaGetSymbolAddress((void**)&qkl,  g_qk_lo);
    cudaGetSymbolAddress((void**)&ah,   g_a_hi);   cudaGetSymbolAddress((void**)&al,   g_a_lo);
    cudaGetSymbolAddress((void**)&x1,   g_x1);
    cudaGetSymbolAddress((void**)&xn2h, g_xn2_hi); cudaGetSymbolAddress((void**)&xn2l, g_xn2_lo);
    cudaGetSymbolAddress((void**)&hh,   g_h_hi);   cudaGetSymbolAddress((void**)&hl,   g_h_lo);
    cudaGetSymbolAddress((void**)&wqh,  g_wqkuv_hi); cudaGetSymbolAddress((void**)&wql, g_wqkuv_lo);
    cudaGetSymbolAddress((void**)&woh,  g_wout_hi);  cudaGetSymbolAddress((void**)&wol, g_wout_lo);
    cudaGetSymbolAddress((void**)&w1h,  g_w1_hi);    cudaGetSymbolAddress((void**)&w1l, g_w1_lo);
    cudaGetSymbolAddress((void**)&w3h,  g_w3_hi);    cudaGetSymbolAddress((void**)&w3l, g_w3_lo);
    cudaGetSymbolAddress((void**)&w2h,  g_w2_hi);    cudaGetSymbolAddress((void**)&w2l, g_w2_lo);

    cudaFuncSetAttribute(gemm_mma<1>, cudaFuncAttributeMaxDynamicSharedMemorySize, GEMM_SMEM);
    cudaFuncSetAttribute(gemm_mma<3>, cudaFuncAttributeMaxDynamicSharedMemorySize, GEMM_SMEM);
    cudaFuncSetAttribute(gemm_dual,   cudaFuncAttributeMaxDynamicSharedMemorySize, DUAL_SMEM);
    cudaFuncSetAttribute(attn_mma,    cudaFuncAttributeMaxDynamicSharedMemorySize, ATT_SMEM);

    dim3 blk(256);

    // 0. weight transpose + split
    wsplit_kernel<<<dim3(4 * DD / 32, DD / 32), blk>>>(w_qkuv, wqh, wql, DD, 4 * DD);
    wsplit_kernel<<<dim3(DD / 32, DD / 32),     blk>>>(w_out,  woh, wol, DD, DD);
    wsplit_kernel<<<dim3(FF / 32, DD / 32),     blk>>>(w1,     w1h, w1l, DD, FF);
    wsplit_kernel<<<dim3(FF / 32, DD / 32),     blk>>>(w3,     w3h, w3l, DD, FF);
    wsplit_kernel<<<dim3(DD / 32, FF / 32),     blk>>>(w2,     w2h, w2l, FF, DD);

    // 1. LN1 -> split
    ln_split_kernel<<<MROWS, blk>>>(x, ln1_g, ln1_b, xnh, xnl);
    // 2. qkuv = silu(xn @ w_qkuv) -> split bf16
    gemm_mma<3><<<dim3(4 * DD / 128, MROWS / 128), blk, GEMM_SMEM>>>(
        xnh, xnl, wqh, wql, nullptr, nullptr, qkh, qkl, MROWS, 4 * DD, DD);
    // 3. attention -> a hi/lo
    attn_mma<<<dim3(LL / 128, BB * HH), blk, ATT_SMEM>>>(qkh, qkl, na_g, na_b, ah, al);
    // 4. x1 = x + a @ w_out
    gemm_mma<1><<<dim3(DD / 128, MROWS / 128), blk, GEMM_SMEM>>>(
        ah, al, woh, wol, x1, x, nullptr, nullptr, MROWS, DD, DD);
    // 5. LN2 -> split
    ln_split_kernel<<<MROWS, blk>>>(x1, ln2_g, ln2_b, xn2h, xn2l);
    // 6+7. h = silu(xn2@w1) * (xn2@w3) -> split
    gemm_dual<<<dim3(FF / 128, MROWS / 128), blk, DUAL_SMEM>>>(
        xn2h, xn2l, w1h, w1l, w3h, w3l, hh, hl, MROWS, FF, DD);
    // 8. out = x1 + h @ w2
    gemm_mma<1><<<dim3(DD / 128, MROWS / 128), blk, GEMM_SMEM>>>(
        hh, hl, w2h, w2l, out, x1, nullptr, nullptr, MROWS, DD, FF);
}

// round 6
// speedup vs baseline: 2.6983x; 1.0076x over previous
#include <cuda_runtime.h>
#include <cuda_bf16.h>
#include <cstdint>
#include <math.h>

#define BB 2
#define LL 2048
#define DD 1024
#define HH 16
#define HD 64
#define FF 4096
#define MROWS (BB*LL)   // 4096

// ---------------- scratch (device globals) ---------------------------------
__device__ __nv_bfloat16 g_xn_hi [MROWS * DD];
__device__ __nv_bfloat16 g_xn_lo [MROWS * DD];
__device__ __nv_bfloat16 g_qk_hi [MROWS * 4 * DD];   // silu(xn@w_qkuv) split
__device__ __nv_bfloat16 g_qk_lo [MROWS * 4 * DD];
__device__ __nv_bfloat16 g_a_hi  [MROWS * DD];
__device__ __nv_bfloat16 g_a_lo  [MROWS * DD];
__device__ float         g_x1    [MROWS * DD];
__device__ __nv_bfloat16 g_xn2_hi[MROWS * DD];
__device__ __nv_bfloat16 g_xn2_lo[MROWS * DD];
__device__ __nv_bfloat16 g_h_hi  [MROWS * FF];
__device__ __nv_bfloat16 g_h_lo  [MROWS * FF];
// transposed + split weights: [N, K] K-major
__device__ __nv_bfloat16 g_wqkuv_hi[4 * DD * DD];
__device__ __nv_bfloat16 g_wqkuv_lo[4 * DD * DD];
__device__ __nv_bfloat16 g_wout_hi [DD * DD];
__device__ __nv_bfloat16 g_wout_lo [DD * DD];
__device__ __nv_bfloat16 g_w1_hi   [DD * FF];
__device__ __nv_bfloat16 g_w1_lo   [DD * FF];
__device__ __nv_bfloat16 g_w3_hi   [DD * FF];
__device__ __nv_bfloat16 g_w3_lo   [DD * FF];
__device__ __nv_bfloat16 g_w2_hi   [FF * DD];
__device__ __nv_bfloat16 g_w2_lo   [FF * DD];

__device__ __forceinline__ float silu(float x) {
    return __fdividef(x, 1.0f + __expf(-x));
}
__device__ __forceinline__ uint32_t smem_u32(const void* p) {
    uint32_t a;
    asm("{ .reg .u64 t; cvta.to.shared.u64 t, %1; cvt.u32.u64 %0, t; }" : "=r"(a) : "l"(p));
    return a;
}
__device__ __forceinline__ void cp16(uint32_t s, const void* g) {
    asm volatile("cp.async.cg.shared.global [%0], [%1], 16;" :: "r"(s), "l"(g) : "memory");
}
#define CPCOMMIT() asm volatile("cp.async.commit_group;" ::: "memory")
#define CPWAIT(n)  asm volatile("cp.async.wait_group %0;" :: "n"(n) : "memory")
__device__ __forceinline__ void bf_split(float v, __nv_bfloat16& h, __nv_bfloat16& l) {
    h = __float2bfloat16(v);
    l = __float2bfloat16(v - __bfloat162float(h));
}
__device__ __forceinline__ uint32_t pack2(__nv_bfloat16 a, __nv_bfloat16 b) {
    return (uint32_t)__bfloat16_as_ushort(a) | ((uint32_t)__bfloat16_as_ushort(b) << 16);
}
__device__ __forceinline__ void ldsm4(uint32_t* r, uint32_t a) {
    asm volatile("ldmatrix.sync.aligned.m8n8.x4.shared.b16 {%0,%1,%2,%3}, [%4];"
        : "=r"(r[0]), "=r"(r[1]), "=r"(r[2]), "=r"(r[3]) : "r"(a));
}
__device__ __forceinline__ void ldsm4t(uint32_t* r, uint32_t a) {
    asm volatile("ldmatrix.sync.aligned.m8n8.x4.trans.shared.b16 {%0,%1,%2,%3}, [%4];"
        : "=r"(r[0]), "=r"(r[1]), "=r"(r[2]), "=r"(r[3]) : "r"(a));
}
__device__ __forceinline__ void mma16816(float* c, const uint32_t* a, uint32_t b0, uint32_t b1) {
    asm volatile(
        "mma.sync.aligned.m16n8k16.row.col.f32.bf16.bf16.f32 "
        "{%0,%1,%2,%3}, {%4,%5,%6,%7}, {%8,%9}, {%0,%1,%2,%3};"
        : "+f"(c[0]), "+f"(c[1]), "+f"(c[2]), "+f"(c[3])
        : "r"(a[0]), "r"(a[1]), "r"(a[2]), "r"(a[3]), "r"(b0), "r"(b1));
}

// ---------------- weight transpose + split ----------------------------------
__global__ __launch_bounds__(256) void wsplit_kernel(
    const float* __restrict__ w, __nv_bfloat16* __restrict__ whi,
    __nv_bfloat16* __restrict__ wlo, int K, int N)
{
    __shared__ float t[32][33];
    int n0 = blockIdx.x * 32, k0 = blockIdx.y * 32;
    int tx = threadIdx.x & 31, ty = threadIdx.x >> 5;
    #pragma unroll
    for (int j = 0; j < 4; j++)
        t[ty + j * 8][tx] = w[(size_t)(k0 + ty + j * 8) * N + n0 + tx];
    __syncthreads();
    #pragma unroll
    for (int j = 0; j < 4; j++) {
        int nn = ty + j * 8;
        float v = t[tx][nn];
        __nv_bfloat16 h, l; bf_split(v, h, l);
        size_t o = (size_t)(n0 + nn) * K + k0 + tx;
        whi[o] = h; wlo[o] = l;
    }
}

// ---------------- LayerNorm -> split bf16 -----------------------------------
__global__ __launch_bounds__(256) void ln_split_kernel(
    const float* __restrict__ x, const float* __restrict__ g,
    const float* __restrict__ b, __nv_bfloat16* __restrict__ oh,
    __nv_bfloat16* __restrict__ ol)
{
    int row = blockIdx.x;
    const float* xr = x + (size_t)row * DD;
    float s = 0.f, s2 = 0.f;
    for (int i = threadIdx.x; i < DD; i += 256) {
        float v = xr[i]; s += v; s2 += v * v;
    }
    __shared__ float red[8], red2[8], stats[2];
    for (int off = 16; off > 0; off >>= 1) {
        s  += __shfl_down_sync(0xffffffffu, s,  off);
        s2 += __shfl_down_sync(0xffffffffu, s2, off);
    }
    int wid = threadIdx.x >> 5, lid = threadIdx.x & 31;
    if (lid == 0) { red[wid] = s; red2[wid] = s2; }
    __syncthreads();
    if (threadIdx.x == 0) {
        float ts = 0.f, ts2 = 0.f;
        for (int i = 0; i < 8; i++) { ts += red[i]; ts2 += red2[i]; }
        float mu = ts * (1.0f / DD);
        float var = ts2 * (1.0f / DD) - mu * mu;
        stats[0] = mu; stats[1] = rsqrtf(var + 1e-5f);
    }
    __syncthreads();
    float mu = stats[0], rstd = stats[1];
    for (int i = threadIdx.x; i < DD; i += 256) {
        float v = (xr[i] - mu) * rstd * g[i] + b[i];
        __nv_bfloat16 h, l; bf_split(v, h, l);
        oh[(size_t)row * DD + i] = h;
        ol[(size_t)row * DD + i] = l;
    }
}

// ---------------- mma.sync split-bf16 GEMM (3-stage) -------------------------
// MODE 1: Cf = acc + aux (fp32 out).  MODE 3: silu(acc) -> Chi/Clo split.
#define SPAD 72
#define TEN_BYTES (128 * SPAD * 2)
#define STAGE_BYTES (4 * TEN_BYTES)
#define GSTAGES 3
#define GEMM_SMEM (GSTAGES * STAGE_BYTES)   // 221184

template <int MODE>
__global__ __launch_bounds__(256, 1) void gemm_mma(
    const __nv_bfloat16* __restrict__ Ahi, const __nv_bfloat16* __restrict__ Alo,
    const __nv_bfloat16* __restrict__ Bhi, const __nv_bfloat16* __restrict__ Blo,
    float* __restrict__ Cf, const float* __restrict__ aux,
    __nv_bfloat16* __restrict__ Chi, __nv_bfloat16* __restrict__ Clo,
    int M, int N, int K)
{
    extern __shared__ char smem[];
    const uint32_t sbase = smem_u32(smem);
    const int tid = threadIdx.x, lane = tid & 31, wid = tid >> 5;
    const int wm = wid & 1, wn = wid >> 1;
    const int bx = blockIdx.x, by = blockIdx.y;

    const size_t rowbytes = (size_t)K * 2;
    const char* base[4] = {
        (const char*)(Ahi + (size_t)by * 128 * K),
        (const char*)(Alo + (size_t)by * 128 * K),
        (const char*)(Bhi + (size_t)bx * 128 * K),
        (const char*)(Blo + (size_t)bx * 128 * K)
    };

    const uint32_t aRowOff = (uint32_t)((wm * 64 + (lane & 15)) * (SPAD * 2) + (lane >> 4) * 16);
    const int bg = lane >> 3;
    const uint32_t bRowOff = (uint32_t)((wn * 32 + (bg >> 1) * 8 + (lane & 7)) * (SPAD * 2) + (bg & 1) * 16);

    auto load_slab = [&](int ks, int st) {
        uint32_t stg = sbase + (uint32_t)st * STAGE_BYTES;
        size_t koff = (size_t)ks * 128;
        #pragma unroll
        for (int i = 0; i < 16; i++) {
            int c = tid + i * 256;
            int tn = c >> 10;
            int rr = (c >> 3) & 127;
            int ck = (c & 7) * 16;
            cp16(stg + (uint32_t)(tn * TEN_BYTES + rr * (SPAD * 2) + ck),
                 base[tn] + (size_t)rr * rowbytes + koff + ck);
        }
        CPCOMMIT();
    };

    float acc[4][4][4];
    #pragma unroll
    for (int mt = 0; mt < 4; mt++)
        #pragma unroll
        for (int nt = 0; nt < 4; nt++)
            #pragma unroll
            for (int j = 0; j < 4; j++) acc[mt][nt][j] = 0.f;

    const int ns = K >> 6;
    load_slab(0, 0);
    if (ns > 1) load_slab(1, 1);

    for (int i = 0; i < ns; i++) {
        if (i + 1 < ns) CPWAIT(1);
        else            CPWAIT(0);
        __syncthreads();
        if (i + 2 < ns) load_slab(i + 2, (i + 2) % GSTAGES);

        uint32_t stg = sbase + (uint32_t)(i % GSTAGES) * STAGE_BYTES;
        uint32_t aHiB = stg + aRowOff;
        uint32_t aLoB = stg + TEN_BYTES + aRowOff;
        uint32_t bHiB = stg + 2 * TEN_BYTES + bRowOff;
        uint32_t bLoB = stg + 3 * TEN_BYTES + bRowOff;

        #pragma unroll
        for (int ks = 0; ks < 4; ks++) {
            uint32_t ah[4][4], al[4][4], bh[2][4], bl[2][4];
            #pragma unroll
            for (int mt = 0; mt < 4; mt++) {
                uint32_t o = (uint32_t)(mt * 16 * (SPAD * 2) + ks * 32);
                ldsm4(ah[mt], aHiB + o);
                ldsm4(al[mt], aLoB + o);
            }
            #pragma unroll
            for (int p = 0; p < 2; p++) {
                uint32_t o = (uint32_t)(p * 16 * (SPAD * 2) + ks * 32);
                ldsm4(bh[p], bHiB + o);
                ldsm4(bl[p], bLoB + o);
            }
            #pragma unroll
            for (int mt = 0; mt < 4; mt++) {
                #pragma unroll
                for (int nt = 0; nt < 4; nt++) {
                    int p = nt >> 1, o = (nt & 1) * 2;
                    mma16816(acc[mt][nt], ah[mt], bh[p][o], bh[p][o + 1]);
                    mma16816(acc[mt][nt], ah[mt], bl[p][o], bl[p][o + 1]);
                    mma16816(acc[mt][nt], al[mt], bh[p][o], bh[p][o + 1]);
                }
            }
        }
    }

    const int groupID = lane >> 2, tid4 = lane & 3;
    #pragma unroll
    for (int mt = 0; mt < 4; mt++) {
        int r0 = by * 128 + wm * 64 + mt * 16 + groupID;
        #pragma unroll
        for (int nt = 0; nt < 4; nt++) {
            int cg = bx * 128 + wn * 32 + nt * 8 + tid4 * 2;
            float* a = acc[mt][nt];
            #pragma unroll
            for (int half = 0; half < 2; half++) {
                size_t off = (size_t)(r0 + half * 8) * N + cg;
                float v0 = a[half * 2 + 0], v1 = a[half * 2 + 1];
                if (MODE == 1) {
                    float2 ax = *(const float2*)(aux + off);
                    float2 o; o.x = v0 + ax.x; o.y = v1 + ax.y;
                    *(float2*)(Cf + off) = o;
                } else {
                    float t0 = silu(v0), t1 = silu(v1);
                    __nv_bfloat16 h0, l0, h1, l1;
                    bf_split(t0, h0, l0);
                    bf_split(t1, h1, l1);
                    *(uint32_t*)(Chi + off) = pack2(h0, h1);
                    *(uint32_t*)(Clo + off) = pack2(l0, l1);
                }
            }
        }
    }
}

// ---------------- dual GEMM: h = silu(A@W1) * (A@W3) -> split ----------------
#define DSTAGE_BYTES (6 * TEN_BYTES)      // 110592
#define DUAL_SMEM (2 * DSTAGE_BYTES)      // 221184

__global__ __launch_bounds__(256, 1) void gemm_dual(
    const __nv_bfloat16* __restrict__ Ahi, const __nv_bfloat16* __restrict__ Alo,
    const __nv_bfloat16* __restrict__ B1hi, const __nv_bfloat16* __restrict__ B1lo,
    const __nv_bfloat16* __restrict__ B3hi, const __nv_bfloat16* __restrict__ B3lo,
    __nv_bfloat16* __restrict__ Chi, __nv_bfloat16* __restrict__ Clo,
    int M, int N, int K)
{
    extern __shared__ char smem[];
    const uint32_t sbase = smem_u32(smem);
    const int tid = threadIdx.x, lane = tid & 31, wid = tid >> 5;
    const int wm = wid & 1, wn = wid >> 1;
    const int bx = blockIdx.x, by = blockIdx.y;

    const size_t rowbytes = (size_t)K * 2;
    const char* base[6] = {
        (const char*)(Ahi  + (size_t)by * 128 * K),
        (const char*)(Alo  + (size_t)by * 128 * K),
        (const char*)(B1hi + (size_t)bx * 128 * K),
        (const char*)(B1lo + (size_t)bx * 128 * K),
        (const char*)(B3hi + (size_t)bx * 128 * K),
        (const char*)(B3lo + (size_t)bx * 128 * K)
    };

    const uint32_t aRowOff = (uint32_t)((wm * 64 + (lane & 15)) * (SPAD * 2) + (lane >> 4) * 16);
    const int bg = lane >> 3;
    const uint32_t bRowOff = (uint32_t)((wn * 32 + (bg >> 1) * 8 + (lane & 7)) * (SPAD * 2) + (bg & 1) * 16);

    auto load_slab = [&](int ks, int st) {
        uint32_t stg = sbase + (uint32_t)st * DSTAGE_BYTES;
        size_t koff = (size_t)ks * 128;
        #pragma unroll
        for (int i = 0; i < 24; i++) {
            int c = tid + i * 256;
            int tn = c >> 10;
            int rr = (c >> 3) & 127;
            int ck = (c & 7) * 16;
            cp16(stg + (uint32_t)(tn * TEN_BYTES + rr * (SPAD * 2) + ck),
                 base[tn] + (size_t)rr * rowbytes + koff + ck);
        }
        CPCOMMIT();
    };

    float acc1[4][4][4], acc3[4][4][4];
    #pragma unroll
    for (int mt = 0; mt < 4; mt++)
        #pragma unroll
        for (int nt = 0; nt < 4; nt++)
            #pragma unroll
            for (int j = 0; j < 4; j++) { acc1[mt][nt][j] = 0.f; acc3[mt][nt][j] = 0.f; }

    const int ns = K >> 6;
    load_slab(0, 0);

    for (int i = 0; i < ns; i++) {
        CPWAIT(0);
        __syncthreads();
        if (i + 1 < ns) load_slab(i + 1, (i + 1) & 1);

        uint32_t stg = sbase + (uint32_t)(i & 1) * DSTAGE_BYTES;
        uint32_t aHiB  = stg + aRowOff;
        uint32_t aLoB  = stg + TEN_BYTES + aRowOff;
        uint32_t b1HiB = stg + 2 * TEN_BYTES + bRowOff;
        uint32_t b1LoB = stg + 3 * TEN_BYTES + bRowOff;
        uint32_t b3HiB = stg + 4 * TEN_BYTES + bRowOff;
        uint32_t b3LoB = stg + 5 * TEN_BYTES + bRowOff;

        #pragma unroll
        for (int ks = 0; ks < 4; ks++) {
            uint32_t ah[4][4], al[4][4], bh[2][4], bl[2][4];
            #pragma unroll
            for (int mt = 0; mt < 4; mt++) {
                uint32_t o = (uint32_t)(mt * 16 * (SPAD * 2) + ks * 32);
                ldsm4(ah[mt], aHiB + o);
                ldsm4(al[mt], aLoB + o);
            }
            #pragma unroll
            for (int p = 0; p < 2; p++) {
                uint32_t o = (uint32_t)(p * 16 * (SPAD * 2) + ks * 32);
                ldsm4(bh[p], b1HiB + o);
                ldsm4(bl[p], b1LoB + o);
            }
            #pragma unroll
            for (int mt = 0; mt < 4; mt++)
                #pragma unroll
                for (int nt = 0; nt < 4; nt++) {
                    int p = nt >> 1, o = (nt & 1) * 2;
                    mma16816(acc1[mt][nt], ah[mt], bh[p][o], bh[p][o + 1]);
                    mma16816(acc1[mt][nt], ah[mt], bl[p][o], bl[p][o + 1]);
                    mma16816(acc1[mt][nt], al[mt], bh[p][o], bh[p][o + 1]);
                }
            #pragma unroll
            for (int p = 0; p < 2; p++) {
                uint32_t o = (uint32_t)(p * 16 * (SPAD * 2) + ks * 32);
                ldsm4(bh[p], b3HiB + o);
                ldsm4(bl[p], b3LoB + o);
            }
            #pragma unroll
            for (int mt = 0; mt < 4; mt++)
                #pragma unroll
                for (int nt = 0; nt < 4; nt++) {
                    int p = nt >> 1, o = (nt & 1) * 2;
                    mma16816(acc3[mt][nt], ah[mt], bh[p][o], bh[p][o + 1]);
                    mma16816(acc3[mt][nt], ah[mt], bl[p][o], bl[p][o + 1]);
                    mma16816(acc3[mt][nt], al[mt], bh[p][o], bh[p][o + 1]);
                }
        }
    }

    const int groupID = lane >> 2, tid4 = lane & 3;
    #pragma unroll
    for (int mt = 0; mt < 4; mt++) {
        int r0 = by * 128 + wm * 64 + mt * 16 + groupID;
        #pragma unroll
        for (int nt = 0; nt < 4; nt++) {
            int cg = bx * 128 + wn * 32 + nt * 8 + tid4 * 2;
            #pragma unroll
            for (int half = 0; half < 2; half++) {
                size_t off = (size_t)(r0 + half * 8) * N + cg;
                float t0 = silu(acc1[mt][nt][half * 2 + 0]) * acc3[mt][nt][half * 2 + 0];
                float t1 = silu(acc1[mt][nt][half * 2 + 1]) * acc3[mt][nt][half * 2 + 1];
                __nv_bfloat16 h0, l0, h1, l1;
                bf_split(t0, h0, l0);
                bf_split(t1, h1, l1);
                *(uint32_t*)(Chi + off) = pack2(h0, h1);
                *(uint32_t*)(Clo + off) = pack2(l0, l1);
            }
        }
    }
}

// ---------------- Fused attention (pipelined loads, mma.sync) ----------------
// smem: Qh 0, Ql 18432 | K stage0 h/l 36864/55296 | K stage1 h/l 73728/92160 |
//       Vh 110592, Vl 129024 | Sh 147456 (128x136), Sl 182272. total 217088.
#define AROWB 144
#define SROWB 272
#define ATT_SMEM 217088
#define GROWB 8192     // global row stride of qkuv split arrays (4096 bf16)

__global__ __launch_bounds__(256, 1) void attn_mma(
    const __nv_bfloat16* __restrict__ qkh, const __nv_bfloat16* __restrict__ qkl,
    const float* __restrict__ nag, const float* __restrict__ nab,
    __nv_bfloat16* __restrict__ ahi, __nv_bfloat16* __restrict__ alo)
{
    extern __shared__ char smc[];
    const uint32_t sb = smem_u32(smc);
    const uint32_t oQh = 0, oQl = 18432;
    const uint32_t oKh[2] = {36864, 73728};
    const uint32_t oKl[2] = {55296, 92160};
    const uint32_t oVh = 110592, oVl = 129024;
    const uint32_t oSh = 147456, oSl = 182272;
    __nv_bfloat16* shp = (__nv_bfloat16*)(smc + oSh);
    __nv_bfloat16* slp = (__nv_bfloat16*)(smc + oSl);
    float* aS = (float*)(smc + oSh);
    __shared__ float mu_s[128], rs_s[128];

    const int qb = (int)gridDim.x - 1 - (int)blockIdx.x;   // heavy blocks first
    const int bh = blockIdx.y;
    const int b = bh >> 4, h = bh & 15;
    const int tid = threadIdx.x, lane = tid & 31, wid = tid >> 5;
    const int wm = wid & 1, wn = wid >> 1;
    const int groupID = lane >> 2, tid4 = lane & 3;

    const char* gh = (const char*)qkh + (size_t)(b * LL) * GROWB + h * 128;
    const char* gl = (const char*)qkl + (size_t)(b * LL) * GROWB + h * 128;

    auto ldt = [&](uint32_t so, const char* g) {
        #pragma unroll
        for (int i = 0; i < 4; i++) {
            int idx = tid + i * 256;
            int r = idx >> 3, ck = (idx & 7) * 16;
            cp16(sb + so + (uint32_t)(r * AROWB + ck), g + (size_t)r * GROWB + ck);
        }
    };

    // Prologue: Q tiles + K(0) in one group
    ldt(oQh, gh + (size_t)(qb * 128) * GROWB);
    ldt(oQl, gl + (size_t)(qb * 128) * GROWB);
    ldt(oKh[0], gh + 2048 + (size_t)0 * GROWB);
    ldt(oKl[0], gl + 2048 + (size_t)0 * GROWB);
    CPCOMMIT();

    const uint32_t aOffQ = (uint32_t)((wm * 64 + (lane & 15)) * AROWB + (lane >> 4) * 16);
    const int bg = lane >> 3;
    const uint32_t bOffK = (uint32_t)((wn * 32 + (bg >> 1) * 8 + (lane & 7)) * AROWB + (bg & 1) * 16);
    const uint32_t aOffS = (uint32_t)((wm * 64 + (lane & 15)) * SROWB + (lane >> 4) * 16);
    const uint32_t bOffV = (uint32_t)(((bg & 1) * 8 + (lane & 7)) * AROWB + (wn * 16 + (bg >> 1) * 8) * 2);

    float oacc[4][2][4];
    #pragma unroll
    for (int mt = 0; mt < 4; mt++)
        #pragma unroll
        for (int nt = 0; nt < 2; nt++)
            #pragma unroll
            for (int j = 0; j < 4; j++) oacc[mt][nt][j] = 0.f;

    for (int kb = 0; kb <= qb; kb++) {
        const int st = kb & 1;
        const bool more = (kb < qb);
        __syncthreads();   // prev iter done reading V and S smem
        // issue V(kb)
        ldt(oVh, gh + 4096 + (size_t)(kb * 128) * GROWB);
        ldt(oVl, gl + 4096 + (size_t)(kb * 128) * GROWB);
        CPCOMMIT();
        // prefetch K(kb+1) into the other stage
        if (more) {
            ldt(oKh[st ^ 1], gh + 2048 + (size_t)((kb + 1) * 128) * GROWB);
            ldt(oKl[st ^ 1], gl + 2048 + (size_t)((kb + 1) * 128) * GROWB);
            CPCOMMIT();
        }
        // wait for K(kb) (leave V(kb) [+K(kb+1)] in flight)
        if (more) CPWAIT(2); else CPWAIT(1);
        __syncthreads();

        // ---- S = Q @ K^T (3-term) ----
        float sacc[4][4][4];
        #pragma unroll
        for (int mt = 0; mt < 4; mt++)
            #pragma unroll
            for (int nt = 0; nt < 4; nt++)
                #pragma unroll
                for (int j = 0; j < 4; j++) sacc[mt][nt][j] = 0.f;

        #pragma unroll
        for (int ks = 0; ks < 4; ks++) {
            uint32_t qh4[4][4], ql4[4][4], kh4[2][4], kl4[2][4];
            #pragma unroll
            for (int mt = 0; mt < 4; mt++) {
                uint32_t o = (uint32_t)(mt * 16 * AROWB + ks * 32);
                ldsm4(qh4[mt], sb + oQh + aOffQ + o);
                ldsm4(ql4[mt], sb + oQl + aOffQ + o);
            }
            #pragma unroll
            for (int p = 0; p < 2; p++) {
                uint32_t o = (uint32_t)(p * 16 * AROWB + ks * 32);
                ldsm4(kh4[p], sb + oKh[st] + bOffK + o);
                ldsm4(kl4[p], sb + oKl[st] + bOffK + o);
            }
            #pragma unroll
            for (int mt = 0; mt < 4; mt++)
                #pragma unroll
                for (int nt = 0; nt < 4; nt++) {
                    int p = nt >> 1, o = (nt & 1) * 2;
                    mma16816(sacc[mt][nt], qh4[mt], kh4[p][o], kh4[p][o + 1]);
                    mma16816(sacc[mt][nt], qh4[mt], kl4[p][o], kl4[p][o + 1]);
                    mma16816(sacc[mt][nt], ql4[mt], kh4[p][o], kh4[p][o + 1]);
                }
        }

        // ---- silu/scale/mask -> S split to smem ----
        const bool diag = (kb == qb);
        #pragma unroll
        for (int mt = 0; mt < 4; mt++) {
            #pragma unroll
            for (int half = 0; half < 2; half++) {
                int r = wm * 64 + mt * 16 + groupID + half * 8;
                #pragma unroll
                for (int nt = 0; nt < 4; nt++) {
                    int c = wn * 32 + nt * 8 + tid4 * 2;
                    float s0 = silu(sacc[mt][nt][half * 2 + 0] * 0.125f);
                    float s1 = silu(sacc[mt][nt][half * 2 + 1] * 0.125f);
                    if (diag) {
                        if (c > r) s0 = 0.f;
                        if (c + 1 > r) s1 = 0.f;
                    }
                    __nv_bfloat16 h0, l0, h1, l1;
                    bf_split(s0, h0, l0); bf_split(s1, h1, l1);
                    *(uint32_t*)(shp + r * 136 + c) = pack2(h0, h1);
                    *(uint32_t*)(slp + r * 136 + c) = pack2(l0, l1);
                }
            }
        }
        // wait for V(kb) (K(kb+1) may remain in flight)
        if (more) CPWAIT(1); else CPWAIT(0);
        __syncthreads();

        // ---- A += S @ V (3-term, V via ldsm.trans) ----
        #pragma unroll
        for (int ks = 0; ks < 8; ks++) {
            uint32_t sh4[4][4], sl4[4][4], vh4[4], vl4[4];
            #pragma unroll
            for (int mt = 0; mt < 4; mt++) {
                uint32_t o = (uint32_t)(mt * 16 * SROWB + ks * 32);
                ldsm4(sh4[mt], sb + oSh + aOffS + o);
                ldsm4(sl4[mt], sb + oSl + aOffS + o);
            }
            uint32_t vo = (uint32_t)(ks * 16 * AROWB);
            ldsm4t(vh4, sb + oVh + bOffV + vo);
            ldsm4t(vl4, sb + oVl + bOffV + vo);
            #pragma unroll
            for (int mt = 0; mt < 4; mt++)
                #pragma unroll
                for (int nt = 0; nt < 2; nt++) {
                    int o = nt * 2;
                    mma16816(oacc[mt][nt], sh4[mt], vh4[o], vh4[o + 1]);
                    mma16816(oacc[mt][nt], sh4[mt], vl4[o], vl4[o + 1]);
                    mma16816(oacc[mt][nt], sl4[mt], vh4[o], vh4[o + 1]);
                }
        }
    }

    // ---- headLN(d=64) * u, split out ----
    __syncthreads();
    #pragma unroll
    for (int mt = 0; mt < 4; mt++)
        #pragma unroll
        for (int half = 0; half < 2; half++) {
            int r = wm * 64 + mt * 16 + groupID + half * 8;
            #pragma unroll
            for (int nt = 0; nt < 2; nt++) {
                int c = wn * 16 + nt * 8 + tid4 * 2;
                float2 v;
                v.x = oacc[mt][nt][half * 2 + 0];
                v.y = oacc[mt][nt][half * 2 + 1];
                *(float2*)(aS + r * 68 + c) = v;
            }
        }
    __syncthreads();
    if (tid < 128) {
        float s = 0.f, s2 = 0.f;
        #pragma unroll
        for (int c = 0; c < 64; c++) {
            float v = aS[tid * 68 + c];
            s += v; s2 += v * v;
        }
        float mu = s * (1.0f / 64.0f);
        float var = s2 * (1.0f / 64.0f) - mu * mu;
        mu_s[tid] = mu;
        rs_s[tid] = rsqrtf(var + 1e-5f);
    }
    __syncthreads();
    {
        int r = tid >> 1;
        int c0 = (tid & 1) * 32;
        int l = qb * 128 + r;
        float mu = mu_s[r], rstd = rs_s[r];
        const __nv_bfloat16* uh = (const __nv_bfloat16*)(gh + 6144 + (size_t)l * GROWB);
        const __nv_bfloat16* ul = (const __nv_bfloat16*)(gl + 6144 + (size_t)l * GROWB);
        size_t obase = (size_t)(b * LL + l) * DD + h * HD;
        #pragma unroll
        for (int c = c0; c < c0 + 32; c += 2) {
            float u0 = __bfloat162float(uh[c + 0]) + __bfloat162float(ul[c + 0]);
            float u1 = __bfloat162float(uh[c + 1]) + __bfloat162float(ul[c + 1]);
            float t0 = ((aS[r * 68 + c + 0] - mu) * rstd * nag[c + 0] + nab[c + 0]) * u0;
            float t1 = ((aS[r * 68 + c + 1] - mu) * rstd * nag[c + 1] + nab[c + 1]) * u1;
            __nv_bfloat16 h0, l0, h1, l1;
            bf_split(t0, h0, l0); bf_split(t1, h1, l1);
            *(uint32_t*)(ahi + obase + c) = pack2(h0, h1);
            *(uint32_t*)(alo + obase + c) = pack2(l0, l1);
        }
    }
}

// ---------------- host -------------------------------------------------------
extern "C" void kernel_launch(void* const* d_in, const int* in_sizes, int n_in,
                              void* d_out, int out_size)
{
    const float* x      = (const float*)d_in[0];
    const float* w_qkuv = (const float*)d_in[2];
    const float* w_out  = (const float*)d_in[3];
    const float* w1     = (const float*)d_in[4];
    const float* w2     = (const float*)d_in[5];
    const float* w3     = (const float*)d_in[6];
    const float* ln1_g  = (const float*)d_in[7];
    const float* ln1_b  = (const float*)d_in[8];
    const float* ln2_g  = (const float*)d_in[9];
    const float* ln2_b  = (const float*)d_in[10];
    const float* na_g   = (const float*)d_in[11];
    const float* na_b   = (const float*)d_in[12];
    float* out = (float*)d_out;

    __nv_bfloat16 *xnh, *xnl, *qkh, *qkl, *ah, *al, *xn2h, *xn2l, *hh, *hl;
    __nv_bfloat16 *wqh, *wql, *woh, *wol, *w1h, *w1l, *w3h, *w3l, *w2h, *w2l;
    float *x1;
    cudaGetSymbolAddress((void**)&xnh,  g_xn_hi);  cudaGetSymbolAddress((void**)&xnl,  g_xn_lo);
    cudaGetSymbolAddress((void**)&qkh,  g_qk_hi);  cudaGetSymbolAddress((void**)&qkl,  g_qk_lo);
    cudaGetSymbolAddress((void**)&ah,   g_a_hi);   cudaGetSymbolAddress((void**)&al,   g_a_lo);
    cudaGetSymbolAddress((void**)&x1,   g_x1);
    cudaGetSymbolAddress((void**)&xn2h, g_xn2_hi); cudaGetSymbolAddress((void**)&xn2l, g_xn2_lo);
    cudaGetSymbolAddress((void**)&hh,   g_h_hi);   cudaGetSymbolAddress((void**)&hl,   g_h_lo);
    cudaGetSymbolAddress((void**)&wqh,  g_wqkuv_hi); cudaGetSymbolAddress((void**)&wql, g_wqkuv_lo);
    cudaGetSymbolAddress((void**)&woh,  g_wout_hi);  cudaGetSymbolAddress((void**)&wol, g_wout_lo);
    cudaGetSymbolAddress((void**)&w1h,  g_w1_hi);    cudaGetSymbolAddress((void**)&w1l, g_w1_lo);
    cudaGetSymbolAddress((void**)&w3h,  g_w3_hi);    cudaGetSymbolAddress((void**)&w3l, g_w3_lo);
    cudaGetSymbolAddress((void**)&w2h,  g_w2_hi);    cudaGetSymbolAddress((void**)&w2l, g_w2_lo);

    cudaFuncSetAttribute(gemm_mma<1>, cudaFuncAttributeMaxDynamicSharedMemorySize, GEMM_SMEM);
    cudaFuncSetAttribute(gemm_mma<3>, cudaFuncAttributeMaxDynamicSharedMemorySize, GEMM_SMEM);
    cudaFuncSetAttribute(gemm_dual,   cudaFuncAttributeMaxDynamicSharedMemorySize, DUAL_SMEM);
    cudaFuncSetAttribute(attn_mma,    cudaFuncAttributeMaxDynamicSharedMemorySize, ATT_SMEM);

    dim3 blk(256);

    // 0. weight transpose + split
    wsplit_kernel<<<dim3(4 * DD / 32, DD / 32), blk>>>(w_qkuv, wqh, wql, DD, 4 * DD);
    wsplit_kernel<<<dim3(DD / 32, DD / 32),     blk>>>(w_out,  woh, wol, DD, DD);
    wsplit_kernel<<<dim3(FF / 32, DD / 32),     blk>>>(w1,     w1h, w1l, DD, FF);
    wsplit_kernel<<<dim3(FF / 32, DD / 32),     blk>>>(w3,     w3h, w3l, DD, FF);
    wsplit_kernel<<<dim3(DD / 32, FF / 32),     blk>>>(w2,     w2h, w2l, FF, DD);

    // 1. LN1 -> split
    ln_split_kernel<<<MROWS, blk>>>(x, ln1_g, ln1_b, xnh, xnl);
    // 2. qkuv = silu(xn @ w_qkuv) -> split bf16
    gemm_mma<3><<<dim3(4 * DD / 128, MROWS / 128), blk, GEMM_SMEM>>>(
        xnh, xnl, wqh, wql, nullptr, nullptr, qkh, qkl, MROWS, 4 * DD, DD);
    // 3. attention -> a hi/lo
    attn_mma<<<dim3(LL / 128, BB * HH), blk, ATT_SMEM>>>(qkh, qkl, na_g, na_b, ah, al);
    // 4. x1 = x + a @ w_out
    gemm_mma<1><<<dim3(DD / 128, MROWS / 128), blk, GEMM_SMEM>>>(
        ah, al, woh, wol, x1, x, nullptr, nullptr, MROWS, DD, DD);
    // 5. LN2 -> split
    ln_split_kernel<<<MROWS, blk>>>(x1, ln2_g, ln2_b, xn2h, xn2l);
    // 6+7. h = silu(xn2@w1) * (xn2@w3) -> split
    gemm_dual<<<dim3(FF / 128, MROWS / 128), blk, DUAL_SMEM>>>(
        xn2h, xn2l, w1h, w1l, w3h, w3l, hh, hl, MROWS, FF, DD);
    // 8. out = x1 + h @ w2
    gemm_mma<1><<<dim3(DD / 128, MROWS / 128), blk, GEMM_SMEM>>>(
        hh, hl, w2h, w2l, out, x1, nullptr, nullptr, MROWS, DD, FF);
}